// round 14
// baseline (speedup 1.0000x reference)
#include <cuda_runtime.h>
#include <cuda_fp16.h>
#include <cstdint>

#define BSZ    8
#define SEQ    1024
#define DMODEL 512
#define NHEAD  8
#define HDIM   64
#define NROWS  (BSZ*SEQ)
#define QKVD   (3*DMODEL)

// Q pre-scale: hd^-0.5 * log2(e)  (scores in log2 domain)
#define QSCALE 0.1803368801111204f

// ---------------------------------------------------------------------------
// Scratch
// ---------------------------------------------------------------------------
__device__ uint16_t g_q      [NROWS * DMODEL];
__device__ uint16_t g_k      [NROWS * DMODEL];
__device__ uint16_t g_v      [NROWS * DMODEL];
__device__ uint16_t g_xb     [NROWS * DMODEL];
__device__ uint16_t g_wqkvb  [DMODEL * QKVD];
__device__ uint16_t g_w1b    [DMODEL * DMODEL];
__device__ uint16_t g_w2b    [DMODEL * DMODEL];
__device__ float    g_attnout[NROWS * DMODEL];
__device__ float    g_x1     [NROWS * DMODEL];
__device__ uint16_t g_x1b    [NROWS * DMODEL];
__device__ uint16_t g_ffb    [NROWS * DMODEL];
__device__ float    g_ff2    [NROWS * DMODEL];
__device__ unsigned g_maskbits[NROWS * (SEQ/32)];

// ---------------------------------------------------------------------------
// helpers
// ---------------------------------------------------------------------------
__device__ __forceinline__ uint32_t packf16(float lo, float hi) {
    uint32_t r;
    asm("cvt.rn.f16x2.f32 %0, %1, %2;" : "=r"(r) : "f"(hi), "f"(lo));
    return r;
}
__device__ __forceinline__ void mma_f16(float d[4], const uint32_t a[4],
                                        const uint32_t b[2], const float c[4]) {
    asm volatile(
        "mma.sync.aligned.m16n8k16.row.col.f32.f16.f16.f32 "
        "{%0,%1,%2,%3}, {%4,%5,%6,%7}, {%8,%9}, {%10,%11,%12,%13};"
        : "=f"(d[0]), "=f"(d[1]), "=f"(d[2]), "=f"(d[3])
        : "r"(a[0]), "r"(a[1]), "r"(a[2]), "r"(a[3]), "r"(b[0]), "r"(b[1]),
          "f"(c[0]), "f"(c[1]), "f"(c[2]), "f"(c[3]));
}
// f16-accumulator variant: C/D are 2 packed f16x2 regs
__device__ __forceinline__ void mma_f16c16(uint32_t d[2], const uint32_t a[4],
                                           const uint32_t b[2]) {
    asm volatile(
        "mma.sync.aligned.m16n8k16.row.col.f16.f16.f16.f16 "
        "{%0,%1}, {%2,%3,%4,%5}, {%6,%7}, {%0,%1};"
        : "+r"(d[0]), "+r"(d[1])
        : "r"(a[0]), "r"(a[1]), "r"(a[2]), "r"(a[3]), "r"(b[0]), "r"(b[1]));
}
__device__ __forceinline__ void cp_async16(uint32_t dst, const void* src) {
    asm volatile("cp.async.cg.shared.global [%0], [%1], 16;"
                 :: "r"(dst), "l"(src));
}
__device__ __forceinline__ void ldm_x4(uint32_t r[4], uint32_t addr) {
    asm volatile("ldmatrix.sync.aligned.m8n8.x4.shared.b16 {%0,%1,%2,%3}, [%4];"
                 : "=r"(r[0]), "=r"(r[1]), "=r"(r[2]), "=r"(r[3]) : "r"(addr));
}
__device__ __forceinline__ void ldm_x4_t(uint32_t r[4], uint32_t addr) {
    asm volatile("ldmatrix.sync.aligned.m8n8.x4.trans.shared.b16 {%0,%1,%2,%3}, [%4];"
                 : "=r"(r[0]), "=r"(r[1]), "=r"(r[2]), "=r"(r[3]) : "r"(addr));
}

// ---------------------------------------------------------------------------
// Mask: per-block dtype detection + vectorized bit expansion
// ---------------------------------------------------------------------------
__global__ __launch_bounds__(256)
void mask_kernel(const void* __restrict__ m, unsigned* __restrict__ out, int n) {
    __shared__ int s3f, soff;
    if (threadIdx.x == 0) { s3f = 0; soff = 0; }
    __syncthreads();
    {
        uint4 v = ((const uint4*)m)[threadIdx.x];
        unsigned w[4] = {v.x, v.y, v.z, v.w};
        int l3f = 0, loff = 0;
#pragma unroll
        for (int j = 0; j < 4; j++) {
            unsigned x = w[j];
            if (((x & 0xFF) == 0x3F) || (((x >> 8) & 0xFF) == 0x3F) ||
                (((x >> 16) & 0xFF) == 0x3F) || (((x >> 24) & 0xFF) == 0x3F))
                l3f++;
            if (x & 0xFFFFFF00u) loff++;
        }
        if (l3f) atomicAdd(&s3f, 1);
        if (loff) atomicAdd(&soff, 1);
    }
    __syncthreads();
    const int kind = (s3f > 0) ? 2 : ((soff > 0) ? 0 : 1);

    const int nthreads = gridDim.x * blockDim.x;
    const int nchunk = n / 16;
    for (int idx = blockIdx.x * blockDim.x + threadIdx.x; idx < nchunk;
         idx += nthreads) {
        unsigned bits = 0;
        if (kind == 0) {
            uint4 v = ((const uint4*)m)[idx];
            unsigned w[4] = {v.x, v.y, v.z, v.w};
#pragma unroll
            for (int j = 0; j < 4; j++)
#pragma unroll
                for (int bpos = 0; bpos < 4; bpos++)
                    if ((w[j] >> (8 * bpos)) & 0xFFu)
                        bits |= 1u << (j * 4 + bpos);
        } else {
            const uint4* p = (const uint4*)m + idx * 4;
#pragma unroll
            for (int j = 0; j < 4; j++) {
                uint4 v = p[j];
                if (v.x) bits |= 1u << (j * 4 + 0);
                if (v.y) bits |= 1u << (j * 4 + 1);
                if (v.z) bits |= 1u << (j * 4 + 2);
                if (v.w) bits |= 1u << (j * 4 + 3);
            }
        }
        unsigned other = __shfl_xor_sync(0xffffffffu, bits, 1);
        if ((threadIdx.x & 1) == 0)
            out[idx >> 1] = bits | (other << 16);
    }
}

// ---------------------------------------------------------------------------
// Fused conversions -> fp16
// ---------------------------------------------------------------------------
#define NX4 (NROWS*DMODEL/4)
#define NW4 (DMODEL*QKVD/4)
#define NF4 (DMODEL*DMODEL/4)

__global__ __launch_bounds__(256)
void convert_kernel(const float* __restrict__ x, const float* __restrict__ wqkv,
                    const float* __restrict__ w1, const float* __restrict__ w2,
                    uint16_t* __restrict__ xb, uint16_t* __restrict__ wqkvb,
                    uint16_t* __restrict__ w1b, uint16_t* __restrict__ w2b) {
    const int total = NX4 + NW4 + 2 * NF4;
    const int stride = gridDim.x * blockDim.x;
    for (int i = blockIdx.x * blockDim.x + threadIdx.x; i < total; i += stride) {
        const float4* src;
        uint2* dst;
        int j;
        if (i < NX4)                      { j = i;               src = (const float4*)x    + j; dst = (uint2*)xb    + j; }
        else if (i < NX4 + NW4)           { j = i - NX4;         src = (const float4*)wqkv + j; dst = (uint2*)wqkvb + j; }
        else if (i < NX4 + NW4 + NF4)     { j = i - NX4 - NW4;   src = (const float4*)w1   + j; dst = (uint2*)w1b   + j; }
        else                              { j = i - NX4-NW4-NF4; src = (const float4*)w2   + j; dst = (uint2*)w2b   + j; }
        float4 v = *src;
        *dst = make_uint2(packf16(v.x, v.y), packf16(v.z, v.w));
    }
}

// ---------------------------------------------------------------------------
// QKV GEMM, fp16, cp.async 3-stage (dynamic smem), ldmatrix.
// ---------------------------------------------------------------------------
#define QA_PITCH 40
#define QB_PITCH 136
#define QA_STAGE (128*QA_PITCH)
#define QB_STAGE (32*QB_PITCH)
#define GEMM_SMEM (3*(QA_STAGE+QB_STAGE)*2)

__global__ __launch_bounds__(256)
void gemm_qkv_f16(const uint16_t* __restrict__ A, const uint16_t* __restrict__ B,
                  const float* __restrict__ bias,
                  uint16_t* __restrict__ Qo, uint16_t* __restrict__ Ko,
                  uint16_t* __restrict__ Vo) {
    extern __shared__ uint16_t dynsmem[];
    uint16_t* As = dynsmem;
    uint16_t* Bs = dynsmem + 3 * QA_STAGE;
    const int K = DMODEL, N = QKVD;
    const int bm = blockIdx.y * 128, bn = blockIdx.x * 128;
    const int tid = threadIdx.x;
    const int wid = tid >> 5, lane = tid & 31;
    const int g = lane >> 2, t = lane & 3;
    const int wm = (wid >> 1) * 32, wn = (wid & 1) * 64;
    const int tsel = lane >> 3, r = lane & 7;

    const uint32_t asB = (uint32_t)__cvta_generic_to_shared(As);
    const uint32_t bsB = (uint32_t)__cvta_generic_to_shared(Bs);

    float acc[2][8][4];
#pragma unroll
    for (int i = 0; i < 2; i++)
#pragma unroll
        for (int j = 0; j < 8; j++)
#pragma unroll
            for (int k = 0; k < 4; k++) acc[i][j][k] = 0.0f;

    auto issue = [&](int stg, int k0) {
#pragma unroll
        for (int i = 0; i < 2; i++) {
            int f = tid + i * 256;
            int row = f >> 2, ch = f & 3;
            cp_async16(asB + (stg * QA_STAGE + row * QA_PITCH) * 2 + ch * 16,
                       &A[(size_t)(bm + row) * K + k0 + ch * 8]);
        }
#pragma unroll
        for (int i = 0; i < 2; i++) {
            int f = tid + i * 256;
            int row = f >> 4, ch = f & 15;
            cp_async16(bsB + (stg * QB_STAGE + row * QB_PITCH) * 2 + ch * 16,
                       &B[(size_t)(k0 + row) * N + bn + ch * 8]);
        }
    };

    const int NIT = K / 32;
    issue(0, 0);
    asm volatile("cp.async.commit_group;");
    issue(1, 32);
    asm volatile("cp.async.commit_group;");

    for (int it = 0; it < NIT; ++it) {
        int cur = it % 3;
        if (it + 2 < NIT) issue((it + 2) % 3, (it + 2) * 32);
        asm volatile("cp.async.commit_group;");
        asm volatile("cp.async.wait_group 2;");
        __syncthreads();

        uint32_t aBase = asB + cur * QA_STAGE * 2;
        uint32_t bBase = bsB + cur * QB_STAGE * 2;
#pragma unroll
        for (int ks = 0; ks < 32; ks += 16) {
            uint32_t aF[2][4];
#pragma unroll
            for (int mt = 0; mt < 2; mt++) {
                int row = wm + mt * 16 + ((tsel & 1) ? 8 : 0) + r;
                int col = ks + ((tsel & 2) ? 8 : 0);
                ldm_x4(aF[mt], aBase + row * (QA_PITCH * 2) + col * 2);
            }
            uint32_t bF[8][2];
#pragma unroll
            for (int p = 0; p < 4; p++) {
                int krow = ks + ((tsel & 1) ? 8 : 0) + r;
                int ncol = wn + p * 16 + ((tsel & 2) ? 8 : 0);
                uint32_t rr[4];
                ldm_x4_t(rr, bBase + krow * (QB_PITCH * 2) + ncol * 2);
                bF[2 * p][0] = rr[0]; bF[2 * p][1] = rr[1];
                bF[2 * p + 1][0] = rr[2]; bF[2 * p + 1][1] = rr[3];
            }
#pragma unroll
            for (int mt = 0; mt < 2; mt++)
#pragma unroll
                for (int nt = 0; nt < 8; nt++)
                    mma_f16(acc[mt][nt], aF[mt], bF[nt], acc[mt][nt]);
        }
        __syncthreads();
    }

#pragma unroll
    for (int mt = 0; mt < 2; mt++) {
        int row = bm + wm + mt * 16 + g;
#pragma unroll
        for (int nt = 0; nt < 8; nt++) {
            int col = bn + wn + nt * 8 + 2 * t;
            float b0 = bias[col], b1 = bias[col + 1];
            float c0 = acc[mt][nt][0] + b0;
            float c1 = acc[mt][nt][1] + b1;
            float c2 = acc[mt][nt][2] + b0;
            float c3 = acc[mt][nt][3] + b1;
            if (col < DMODEL) {
                *(uint32_t*)&Qo[(size_t)row * DMODEL + col] =
                    packf16(c0 * QSCALE, c1 * QSCALE);
                *(uint32_t*)&Qo[(size_t)(row + 8) * DMODEL + col] =
                    packf16(c2 * QSCALE, c3 * QSCALE);
            } else if (col < 2 * DMODEL) {
                int ck = col - DMODEL;
                *(uint32_t*)&Ko[(size_t)row * DMODEL + ck] = packf16(c0, c1);
                *(uint32_t*)&Ko[(size_t)(row + 8) * DMODEL + ck] = packf16(c2, c3);
            } else {
                int cv = col - 2 * DMODEL;
                *(uint32_t*)&Vo[(size_t)row * DMODEL + cv] = packf16(c0, c1);
                *(uint32_t*)&Vo[(size_t)(row + 8) * DMODEL + cv] = packf16(c2, c3);
            }
        }
    }
}

// ---------------------------------------------------------------------------
// Generic fp16 GEMM (FFN), cp.async 3-stage (dynamic smem).
// ---------------------------------------------------------------------------
template<bool RELU, bool OUTHF>
__global__ __launch_bounds__(256)
void gemm_f16(const uint16_t* __restrict__ A, const uint16_t* __restrict__ B,
              const float* __restrict__ bias, float* __restrict__ Cf,
              uint16_t* __restrict__ Cb, int M, int N, int K) {
    extern __shared__ uint16_t dynsmem[];
    uint16_t* As = dynsmem;
    uint16_t* Bs = dynsmem + 3 * QA_STAGE;
    const int bm = blockIdx.y * 128, bn = blockIdx.x * 128;
    const int tid = threadIdx.x;
    const int wid = tid >> 5, lane = tid & 31;
    const int g = lane >> 2, t = lane & 3;
    const int wm = (wid >> 1) * 32, wn = (wid & 1) * 64;
    const int tsel = lane >> 3, r = lane & 7;

    const uint32_t asB = (uint32_t)__cvta_generic_to_shared(As);
    const uint32_t bsB = (uint32_t)__cvta_generic_to_shared(Bs);

    float acc[2][8][4];
#pragma unroll
    for (int i = 0; i < 2; i++)
#pragma unroll
        for (int j = 0; j < 8; j++)
#pragma unroll
            for (int k = 0; k < 4; k++) acc[i][j][k] = 0.0f;

    auto issue = [&](int stg, int k0) {
#pragma unroll
        for (int i = 0; i < 2; i++) {
            int f = tid + i * 256;
            int row = f >> 2, ch = f & 3;
            cp_async16(asB + (stg * QA_STAGE + row * QA_PITCH) * 2 + ch * 16,
                       &A[(size_t)(bm + row) * K + k0 + ch * 8]);
        }
#pragma unroll
        for (int i = 0; i < 2; i++) {
            int f = tid + i * 256;
            int row = f >> 4, ch = f & 15;
            cp_async16(bsB + (stg * QB_STAGE + row * QB_PITCH) * 2 + ch * 16,
                       &B[(size_t)(k0 + row) * N + bn + ch * 8]);
        }
    };

    const int NIT = K / 32;
    issue(0, 0);
    asm volatile("cp.async.commit_group;");
    issue(1, 32);
    asm volatile("cp.async.commit_group;");

    for (int it = 0; it < NIT; ++it) {
        int cur = it % 3;
        if (it + 2 < NIT) issue((it + 2) % 3, (it + 2) * 32);
        asm volatile("cp.async.commit_group;");
        asm volatile("cp.async.wait_group 2;");
        __syncthreads();

        uint32_t aBase = asB + cur * QA_STAGE * 2;
        uint32_t bBase = bsB + cur * QB_STAGE * 2;
#pragma unroll
        for (int ks = 0; ks < 32; ks += 16) {
            uint32_t aF[2][4];
#pragma unroll
            for (int mt = 0; mt < 2; mt++) {
                int row = wm + mt * 16 + ((tsel & 1) ? 8 : 0) + r;
                int col = ks + ((tsel & 2) ? 8 : 0);
                ldm_x4(aF[mt], aBase + row * (QA_PITCH * 2) + col * 2);
            }
            uint32_t bF[8][2];
#pragma unroll
            for (int p = 0; p < 4; p++) {
                int krow = ks + ((tsel & 1) ? 8 : 0) + r;
                int ncol = wn + p * 16 + ((tsel & 2) ? 8 : 0);
                uint32_t rr[4];
                ldm_x4_t(rr, bBase + krow * (QB_PITCH * 2) + ncol * 2);
                bF[2 * p][0] = rr[0]; bF[2 * p][1] = rr[1];
                bF[2 * p + 1][0] = rr[2]; bF[2 * p + 1][1] = rr[3];
            }
#pragma unroll
            for (int mt = 0; mt < 2; mt++)
#pragma unroll
                for (int nt = 0; nt < 8; nt++)
                    mma_f16(acc[mt][nt], aF[mt], bF[nt], acc[mt][nt]);
        }
        __syncthreads();
    }

#pragma unroll
    for (int mt = 0; mt < 2; mt++) {
        int row = bm + wm + mt * 16 + g;
#pragma unroll
        for (int nt = 0; nt < 8; nt++) {
            int col = bn + wn + nt * 8 + 2 * t;
            float b0 = bias[col], b1 = bias[col + 1];
            float c0 = acc[mt][nt][0] + b0;
            float c1 = acc[mt][nt][1] + b1;
            float c2 = acc[mt][nt][2] + b0;
            float c3 = acc[mt][nt][3] + b1;
            if (RELU) {
                c0 = fmaxf(c0, 0.0f); c1 = fmaxf(c1, 0.0f);
                c2 = fmaxf(c2, 0.0f); c3 = fmaxf(c3, 0.0f);
            }
            if (OUTHF) {
                *(uint32_t*)&Cb[(size_t)row * N + col] = packf16(c0, c1);
                *(uint32_t*)&Cb[(size_t)(row + 8) * N + col] = packf16(c2, c3);
            } else {
                *(float2*)&Cf[(size_t)row * N + col] = make_float2(c0, c1);
                *(float2*)&Cf[(size_t)(row + 8) * N + col] = make_float2(c2, c3);
            }
        }
    }
}

// ---------------------------------------------------------------------------
// FlashAttention (R10 shape): 64 q-rows/block, full 1024 keys, fp16 QK^T
// (f16 acc), fused SMAX+mask, ex2.f16x2, 2-stage cp.async K/V.
// NEW: PV accumulators in packed f16 (halves O register file).
// ---------------------------------------------------------------------------
#define TPITCH 72
#define TSTAGE (64*TPITCH)
#define ATTN_SMEM (2*TSTAGE*2*2)   // 36864 B

__global__ __launch_bounds__(128)
void attn_kernel(const uint16_t* __restrict__ Qm, const uint16_t* __restrict__ Km,
                 const uint16_t* __restrict__ Vm,
                 const unsigned int* __restrict__ maskbits,
                 float* __restrict__ out) {
    extern __shared__ uint16_t dynsmem[];
    uint16_t* Ks = dynsmem;
    uint16_t* Vs = dynsmem + 2 * TSTAGE;

    const int qt = blockIdx.x;
    const int bh = blockIdx.y;
    const int b = bh >> 3, h = bh & 7;
    const int tid = threadIdx.x;
    const int wid = tid >> 5, lane = tid & 31;
    const int g = lane >> 2, t = lane & 3;
    const int tsel = lane >> 3, r = lane & 7;
    const int r0 = wid * 16;

    const int qrow_lo = qt * 64 + r0 + g;
    const size_t growL = (size_t)b * SEQ + qrow_lo;

    const uint32_t ksB = (uint32_t)__cvta_generic_to_shared(Ks);
    const uint32_t vsB = (uint32_t)__cvta_generic_to_shared(Vs);

    uint32_t qa[4][4];
    {
        const uint16_t* qb = Qm + growL * DMODEL + h * HDIM;
#pragma unroll
        for (int ks = 0; ks < 4; ks++) {
            qa[ks][0] = *(const uint32_t*)(qb + ks * 16 + 2 * t);
            qa[ks][1] = *(const uint32_t*)(qb + 8 * DMODEL + ks * 16 + 2 * t);
            qa[ks][2] = *(const uint32_t*)(qb + ks * 16 + 8 + 2 * t);
            qa[ks][3] = *(const uint32_t*)(qb + 8 * DMODEL + ks * 16 + 8 + 2 * t);
        }
    }

    // O accumulators: packed f16 pairs. o16[j][0] = (row g,  cols 2t,2t+1)
    //                                   o16[j][1] = (row g+8, cols 2t,2t+1)
    uint32_t o16[8][2];
#pragma unroll
    for (int j = 0; j < 8; j++) { o16[j][0] = 0; o16[j][1] = 0; }
    float l_lo = 0.0f, l_hi = 0.0f;

    const unsigned int* mbL = maskbits + growL * (SEQ / 32);
    const unsigned int* mbH = mbL + 8 * (SEQ / 32);

    auto issue = [&](int stg, int kt) {
        const size_t rowbase = (size_t)b * SEQ + kt * 64;
#pragma unroll
        for (int i = 0; i < 4; i++) {
            int f = tid + i * 128;
            int row = f >> 3, ch = f & 7;
            size_t src = (rowbase + row) * DMODEL + h * HDIM + ch * 8;
            cp_async16(ksB + (stg * TSTAGE + row * TPITCH) * 2 + ch * 16, &Km[src]);
            cp_async16(vsB + (stg * TSTAGE + row * TPITCH) * 2 + ch * 16, &Vm[src]);
        }
    };

    issue(0, 0);
    asm volatile("cp.async.commit_group;");

    const int NKT = SEQ / 64;
    for (int kt = 0; kt < NKT; kt++) {
        if (kt + 1 < NKT) issue((kt + 1) & 1, kt + 1);
        asm volatile("cp.async.commit_group;");
        asm volatile("cp.async.wait_group 1;");
        __syncthreads();

        const uint32_t kBase = ksB + (kt & 1) * TSTAGE * 2;
        const uint32_t vBase = vsB + (kt & 1) * TSTAGE * 2;

        // S = Q K^T, f16 accumulators
        uint32_t S16[8][2];
#pragma unroll
        for (int j = 0; j < 8; j++) { S16[j][0] = 0; S16[j][1] = 0; }
#pragma unroll
        for (int ks = 0; ks < 4; ks++) {
            uint32_t bK[8][2];
#pragma unroll
            for (int p = 0; p < 4; p++) {
                int key = p * 16 + ((tsel & 2) ? 8 : 0) + r;
                int d = ks * 16 + ((tsel & 1) ? 8 : 0);
                uint32_t rr[4];
                ldm_x4(rr, kBase + key * (TPITCH * 2) + d * 2);
                bK[2 * p][0] = rr[0]; bK[2 * p][1] = rr[1];
                bK[2 * p + 1][0] = rr[2]; bK[2 * p + 1][1] = rr[3];
            }
#pragma unroll
            for (int j = 0; j < 8; j++)
                mma_f16c16(S16[j], qa[ks], bK[j]);
        }

        // Fused SMAX + mask subtract, ex2 -> P (A-frag layout)
        {
            unsigned w0L = mbL[kt * 2], w1L = mbL[kt * 2 + 1];
            unsigned w0H = mbH[kt * 2], w1H = mbH[kt * 2 + 1];
            const int sh = 2 * t;
            auto squash = [&](unsigned w) {
                unsigned x = (w >> sh) & 0x03030303u;
                x |= x >> 4;
                x &= 0x00330033u;
                x |= x >> 8;
                return x & 0xFFFFu;
            };
            unsigned mfL = squash(w0L) | (squash(w1L) << 16);
            unsigned mfH = squash(w0H) | (squash(w1H) << 16);
            uint32_t suml = 0, sumh = 0;
#pragma unroll
            for (int j = 0; j < 8; j++) {
                unsigned fL = mfL >> (4 * j), fH = mfH >> (4 * j);
                uint32_t mw0 = ((fL & 1u) ? 0x7BFFu : 0x4400u)
                             | ((fL & 2u) ? 0x7BFF0000u : 0x44000000u);
                uint32_t mw1 = ((fH & 1u) ? 0x7BFFu : 0x4400u)
                             | ((fH & 2u) ? 0x7BFF0000u : 0x44000000u);
                asm("sub.f16x2 %0, %0, %1;" : "+r"(S16[j][0]) : "r"(mw0));
                asm("sub.f16x2 %0, %0, %1;" : "+r"(S16[j][1]) : "r"(mw1));
                asm("ex2.approx.f16x2 %0, %0;" : "+r"(S16[j][0]));
                asm("ex2.approx.f16x2 %0, %0;" : "+r"(S16[j][1]));
                asm("add.f16x2 %0, %0, %1;" : "+r"(suml) : "r"(S16[j][0]));
                asm("add.f16x2 %0, %0, %1;" : "+r"(sumh) : "r"(S16[j][1]));
            }
            __half2 hl = *reinterpret_cast<__half2*>(&suml);
            __half2 hh = *reinterpret_cast<__half2*>(&sumh);
            l_lo += __low2float(hl) + __high2float(hl);
            l_hi += __low2float(hh) + __high2float(hh);
        }

        // O += P V  (f16 accumulators)
#pragma unroll
        for (int ks = 0; ks < 4; ks++) {
            uint32_t pa[4] = {S16[2*ks][0], S16[2*ks][1],
                              S16[2*ks+1][0], S16[2*ks+1][1]};
            uint32_t bV[8][2];
#pragma unroll
            for (int p = 0; p < 4; p++) {
                int key = ks * 16 + ((tsel & 1) ? 8 : 0) + r;
                int d = p * 16 + ((tsel & 2) ? 8 : 0);
                uint32_t rr[4];
                ldm_x4_t(rr, vBase + key * (TPITCH * 2) + d * 2);
                bV[2 * p][0] = rr[0]; bV[2 * p][1] = rr[1];
                bV[2 * p + 1][0] = rr[2]; bV[2 * p + 1][1] = rr[3];
            }
#pragma unroll
            for (int j = 0; j < 8; j++)
                mma_f16c16(o16[j], pa, bV[j]);
        }
        __syncthreads();
    }

    // Final cross-lane l reduction
    l_lo += __shfl_xor_sync(0xffffffffu, l_lo, 1, 4);
    l_lo += __shfl_xor_sync(0xffffffffu, l_lo, 2, 4);
    l_hi += __shfl_xor_sync(0xffffffffu, l_hi, 1, 4);
    l_hi += __shfl_xor_sync(0xffffffffu, l_hi, 2, 4);

    const float inv_lo = 1.0f / l_lo;
    const float inv_hi = 1.0f / l_hi;
    float* obase = out + growL * DMODEL + h * HDIM;
#pragma unroll
    for (int j = 0; j < 8; j++) {
        int col = j * 8 + 2 * t;
        __half2 lo2 = *reinterpret_cast<__half2*>(&o16[j][0]);
        __half2 hi2 = *reinterpret_cast<__half2*>(&o16[j][1]);
        *(float2*)(obase + col) =
            make_float2(__low2float(lo2) * inv_lo, __high2float(lo2) * inv_lo);
        *(float2*)(obase + 8 * DMODEL + col) =
            make_float2(__low2float(hi2) * inv_hi, __high2float(hi2) * inv_hi);
    }
}

// ---------------------------------------------------------------------------
// Residual + LayerNorm; DUAL also writes fp16 copy
// ---------------------------------------------------------------------------
template<bool DUAL>
__global__ __launch_bounds__(128)
void ln_kernel(const float* __restrict__ a, const float* __restrict__ bb,
               const float* __restrict__ gamma, const float* __restrict__ beta,
               float* __restrict__ out, uint16_t* __restrict__ out_b) {
    __shared__ float red[4];
    const int row = blockIdx.x;
    const int tid = threadIdx.x;
    const size_t base = (size_t)row * DMODEL + tid * 4;

    float4 av = *(const float4*)(a + base);
    float4 bv = *(const float4*)(bb + base);
    float x0 = av.x + bv.x, x1 = av.y + bv.y;
    float x2 = av.z + bv.z, x3 = av.w + bv.w;

    float sum = x0 + x1 + x2 + x3;
#pragma unroll
    for (int o = 16; o; o >>= 1) sum += __shfl_xor_sync(0xffffffffu, sum, o);
    if ((tid & 31) == 0) red[tid >> 5] = sum;
    __syncthreads();
    float mean = (red[0] + red[1] + red[2] + red[3]) * (1.0f / DMODEL);
    __syncthreads();

    float d0 = x0 - mean, d1 = x1 - mean, d2 = x2 - mean, d3 = x3 - mean;
    float sq = d0 * d0 + d1 * d1 + d2 * d2 + d3 * d3;
#pragma unroll
    for (int o = 16; o; o >>= 1) sq += __shfl_xor_sync(0xffffffffu, sq, o);
    if ((tid & 31) == 0) red[tid >> 5] = sq;
    __syncthreads();
    float var = (red[0] + red[1] + red[2] + red[3]) * (1.0f / DMODEL);
    float rs = rsqrtf(var + 1e-5f);

    float4 gv = *(const float4*)(gamma + tid * 4);
    float4 be = *(const float4*)(beta + tid * 4);
    float y0 = d0 * rs * gv.x + be.x;
    float y1 = d1 * rs * gv.y + be.y;
    float y2 = d2 * rs * gv.z + be.z;
    float y3 = d3 * rs * gv.w + be.w;
    *(float4*)(out + base) = make_float4(y0, y1, y2, y3);
    if (DUAL) {
        ((uint2*)out_b)[base / 4] =
            make_uint2(packf16(y0, y1), packf16(y2, y3));
    }
}

// ---------------------------------------------------------------------------
// Launch
// ---------------------------------------------------------------------------
extern "C" void kernel_launch(void* const* d_in, const int* in_sizes, int n_in,
                              void* d_out, int out_size) {
    const float* edge_x    = (const float*)d_in[0];
    const void*  edge_mask =               d_in[1];
    const float* Wqkv      = (const float*)d_in[2];
    const float* bqkv      = (const float*)d_in[3];
    const float* W1        = (const float*)d_in[4];
    const float* b1        = (const float*)d_in[5];
    const float* W2        = (const float*)d_in[6];
    const float* b2        = (const float*)d_in[7];
    const float* gamma1    = (const float*)d_in[8];
    const float* beta1     = (const float*)d_in[9];
    const float* gamma2    = (const float*)d_in[10];
    const float* beta2     = (const float*)d_in[11];
    float* out = (float*)d_out;

    float *attnout, *x1, *ff2;
    uint16_t *qb, *kb, *vb, *xb, *wqkvb, *w1b, *w2b, *x1b, *ffb;
    unsigned int* maskbits;
    cudaGetSymbolAddress((void**)&qb,       g_q);
    cudaGetSymbolAddress((void**)&kb,       g_k);
    cudaGetSymbolAddress((void**)&vb,       g_v);
    cudaGetSymbolAddress((void**)&xb,       g_xb);
    cudaGetSymbolAddress((void**)&wqkvb,    g_wqkvb);
    cudaGetSymbolAddress((void**)&w1b,      g_w1b);
    cudaGetSymbolAddress((void**)&w2b,      g_w2b);
    cudaGetSymbolAddress((void**)&attnout,  g_attnout);
    cudaGetSymbolAddress((void**)&x1,       g_x1);
    cudaGetSymbolAddress((void**)&x1b,      g_x1b);
    cudaGetSymbolAddress((void**)&ffb,      g_ffb);
    cudaGetSymbolAddress((void**)&ff2,      g_ff2);
    cudaGetSymbolAddress((void**)&maskbits, g_maskbits);

    cudaFuncSetAttribute(gemm_qkv_f16,
                         cudaFuncAttributeMaxDynamicSharedMemorySize, GEMM_SMEM);
    cudaFuncSetAttribute(gemm_f16<true, true>,
                         cudaFuncAttributeMaxDynamicSharedMemorySize, GEMM_SMEM);
    cudaFuncSetAttribute(gemm_f16<false, false>,
                         cudaFuncAttributeMaxDynamicSharedMemorySize, GEMM_SMEM);
    cudaFuncSetAttribute(attn_kernel,
                         cudaFuncAttributeMaxDynamicSharedMemorySize, ATTN_SMEM);

    mask_kernel<<<2048, 256>>>(edge_mask, maskbits, BSZ * SEQ * SEQ);
    convert_kernel<<<2688, 256>>>(edge_x, Wqkv, W1, W2, xb, wqkvb, w1b, w2b);

    gemm_qkv_f16<<<dim3(QKVD / 128, NROWS / 128), 256, GEMM_SMEM>>>(
        xb, wqkvb, bqkv, qb, kb, vb);

    attn_kernel<<<dim3(SEQ / 64, BSZ * NHEAD), 128, ATTN_SMEM>>>(
        qb, kb, vb, maskbits, attnout);

    ln_kernel<true><<<NROWS, 128>>>(edge_x, attnout, gamma1, beta1, x1, x1b);

    gemm_f16<true, true><<<dim3(DMODEL / 128, NROWS / 128), 256, GEMM_SMEM>>>(
        x1b, w1b, b1, nullptr, ffb, NROWS, DMODEL, DMODEL);

    gemm_f16<false, false><<<dim3(DMODEL / 128, NROWS / 128), 256, GEMM_SMEM>>>(
        ffb, w2b, b2, ff2, nullptr, NROWS, DMODEL, DMODEL);

    ln_kernel<false><<<NROWS, 128>>>(x1, ff2, gamma2, beta2, out, nullptr);
}

// round 15
// speedup vs baseline: 1.0147x; 1.0147x over previous
#include <cuda_runtime.h>
#include <cuda_fp16.h>
#include <cstdint>

#define BSZ    8
#define SEQ    1024
#define DMODEL 512
#define NHEAD  8
#define HDIM   64
#define NROWS  (BSZ*SEQ)
#define QKVD   (3*DMODEL)

// Q pre-scale: hd^-0.5 * log2(e)  (scores in log2 domain)
#define QSCALE 0.1803368801111204f

// ---------------------------------------------------------------------------
// Scratch
// ---------------------------------------------------------------------------
__device__ uint16_t g_q      [NROWS * DMODEL];
__device__ uint16_t g_k      [NROWS * DMODEL];
__device__ uint16_t g_v      [NROWS * DMODEL];
__device__ uint16_t g_xb     [NROWS * DMODEL];
__device__ uint16_t g_wqkvb  [DMODEL * QKVD];
__device__ uint16_t g_w1b    [DMODEL * DMODEL];
__device__ uint16_t g_w2b    [DMODEL * DMODEL];
__device__ float    g_attnout[NROWS * DMODEL];
__device__ float    g_x1     [NROWS * DMODEL];
__device__ uint16_t g_x1b    [NROWS * DMODEL];
__device__ uint16_t g_ffb    [NROWS * DMODEL];
__device__ float    g_ff2    [NROWS * DMODEL];
__device__ unsigned g_maskbits[NROWS * (SEQ/32)];

// ---------------------------------------------------------------------------
// helpers
// ---------------------------------------------------------------------------
__device__ __forceinline__ uint32_t packf16(float lo, float hi) {
    uint32_t r;
    asm("cvt.rn.f16x2.f32 %0, %1, %2;" : "=r"(r) : "f"(hi), "f"(lo));
    return r;
}
__device__ __forceinline__ void mma_f16(float d[4], const uint32_t a[4],
                                        const uint32_t b[2], const float c[4]) {
    asm volatile(
        "mma.sync.aligned.m16n8k16.row.col.f32.f16.f16.f32 "
        "{%0,%1,%2,%3}, {%4,%5,%6,%7}, {%8,%9}, {%10,%11,%12,%13};"
        : "=f"(d[0]), "=f"(d[1]), "=f"(d[2]), "=f"(d[3])
        : "r"(a[0]), "r"(a[1]), "r"(a[2]), "r"(a[3]), "r"(b[0]), "r"(b[1]),
          "f"(c[0]), "f"(c[1]), "f"(c[2]), "f"(c[3]));
}
// f16-accumulator variant (used for S = QK^T)
__device__ __forceinline__ void mma_f16c16(uint32_t d[2], const uint32_t a[4],
                                           const uint32_t b[2]) {
    asm volatile(
        "mma.sync.aligned.m16n8k16.row.col.f16.f16.f16.f16 "
        "{%0,%1}, {%2,%3,%4,%5}, {%6,%7}, {%0,%1};"
        : "+r"(d[0]), "+r"(d[1])
        : "r"(a[0]), "r"(a[1]), "r"(a[2]), "r"(a[3]), "r"(b[0]), "r"(b[1]));
}
__device__ __forceinline__ void cp_async16(uint32_t dst, const void* src) {
    asm volatile("cp.async.cg.shared.global [%0], [%1], 16;"
                 :: "r"(dst), "l"(src));
}
__device__ __forceinline__ void ldm_x4(uint32_t r[4], uint32_t addr) {
    asm volatile("ldmatrix.sync.aligned.m8n8.x4.shared.b16 {%0,%1,%2,%3}, [%4];"
                 : "=r"(r[0]), "=r"(r[1]), "=r"(r[2]), "=r"(r[3]) : "r"(addr));
}
__device__ __forceinline__ void ldm_x4_t(uint32_t r[4], uint32_t addr) {
    asm volatile("ldmatrix.sync.aligned.m8n8.x4.trans.shared.b16 {%0,%1,%2,%3}, [%4];"
                 : "=r"(r[0]), "=r"(r[1]), "=r"(r[2]), "=r"(r[3]) : "r"(addr));
}

// ---------------------------------------------------------------------------
// Mask: per-block dtype detection + vectorized bit expansion
// ---------------------------------------------------------------------------
__global__ __launch_bounds__(256)
void mask_kernel(const void* __restrict__ m, unsigned* __restrict__ out, int n) {
    __shared__ int s3f, soff;
    if (threadIdx.x == 0) { s3f = 0; soff = 0; }
    __syncthreads();
    {
        uint4 v = ((const uint4*)m)[threadIdx.x];
        unsigned w[4] = {v.x, v.y, v.z, v.w};
        int l3f = 0, loff = 0;
#pragma unroll
        for (int j = 0; j < 4; j++) {
            unsigned x = w[j];
            if (((x & 0xFF) == 0x3F) || (((x >> 8) & 0xFF) == 0x3F) ||
                (((x >> 16) & 0xFF) == 0x3F) || (((x >> 24) & 0xFF) == 0x3F))
                l3f++;
            if (x & 0xFFFFFF00u) loff++;
        }
        if (l3f) atomicAdd(&s3f, 1);
        if (loff) atomicAdd(&soff, 1);
    }
    __syncthreads();
    const int kind = (s3f > 0) ? 2 : ((soff > 0) ? 0 : 1);

    const int nthreads = gridDim.x * blockDim.x;
    const int nchunk = n / 16;
    for (int idx = blockIdx.x * blockDim.x + threadIdx.x; idx < nchunk;
         idx += nthreads) {
        unsigned bits = 0;
        if (kind == 0) {
            uint4 v = ((const uint4*)m)[idx];
            unsigned w[4] = {v.x, v.y, v.z, v.w};
#pragma unroll
            for (int j = 0; j < 4; j++)
#pragma unroll
                for (int bpos = 0; bpos < 4; bpos++)
                    if ((w[j] >> (8 * bpos)) & 0xFFu)
                        bits |= 1u << (j * 4 + bpos);
        } else {
            const uint4* p = (const uint4*)m + idx * 4;
#pragma unroll
            for (int j = 0; j < 4; j++) {
                uint4 v = p[j];
                if (v.x) bits |= 1u << (j * 4 + 0);
                if (v.y) bits |= 1u << (j * 4 + 1);
                if (v.z) bits |= 1u << (j * 4 + 2);
                if (v.w) bits |= 1u << (j * 4 + 3);
            }
        }
        unsigned other = __shfl_xor_sync(0xffffffffu, bits, 1);
        if ((threadIdx.x & 1) == 0)
            out[idx >> 1] = bits | (other << 16);
    }
}

// ---------------------------------------------------------------------------
// Conversions -> fp16 (two variants: main-path and weights-for-FFN)
// ---------------------------------------------------------------------------
#define NX4 (NROWS*DMODEL/4)
#define NW4 (DMODEL*QKVD/4)
#define NF4 (DMODEL*DMODEL/4)

__global__ __launch_bounds__(256)
void convert_main_kernel(const float* __restrict__ x,
                         const float* __restrict__ wqkv,
                         uint16_t* __restrict__ xb,
                         uint16_t* __restrict__ wqkvb) {
    const int total = NX4 + NW4;
    const int stride = gridDim.x * blockDim.x;
    for (int i = blockIdx.x * blockDim.x + threadIdx.x; i < total; i += stride) {
        const float4* src;
        uint2* dst;
        int j;
        if (i < NX4) { j = i;       src = (const float4*)x    + j; dst = (uint2*)xb    + j; }
        else         { j = i - NX4; src = (const float4*)wqkv + j; dst = (uint2*)wqkvb + j; }
        float4 v = *src;
        *dst = make_uint2(packf16(v.x, v.y), packf16(v.z, v.w));
    }
}

__global__ __launch_bounds__(256)
void convert_w12_kernel(const float* __restrict__ w1, const float* __restrict__ w2,
                        uint16_t* __restrict__ w1b, uint16_t* __restrict__ w2b) {
    const int total = 2 * NF4;
    const int stride = gridDim.x * blockDim.x;
    for (int i = blockIdx.x * blockDim.x + threadIdx.x; i < total; i += stride) {
        const float4* src;
        uint2* dst;
        int j;
        if (i < NF4) { j = i;       src = (const float4*)w1 + j; dst = (uint2*)w1b + j; }
        else         { j = i - NF4; src = (const float4*)w2 + j; dst = (uint2*)w2b + j; }
        float4 v = *src;
        *dst = make_uint2(packf16(v.x, v.y), packf16(v.z, v.w));
    }
}

// ---------------------------------------------------------------------------
// QKV GEMM, fp16, cp.async 3-stage (dynamic smem), ldmatrix.
// ---------------------------------------------------------------------------
#define QA_PITCH 40
#define QB_PITCH 136
#define QA_STAGE (128*QA_PITCH)
#define QB_STAGE (32*QB_PITCH)
#define GEMM_SMEM (3*(QA_STAGE+QB_STAGE)*2)

__global__ __launch_bounds__(256)
void gemm_qkv_f16(const uint16_t* __restrict__ A, const uint16_t* __restrict__ B,
                  const float* __restrict__ bias,
                  uint16_t* __restrict__ Qo, uint16_t* __restrict__ Ko,
                  uint16_t* __restrict__ Vo) {
    extern __shared__ uint16_t dynsmem[];
    uint16_t* As = dynsmem;
    uint16_t* Bs = dynsmem + 3 * QA_STAGE;
    const int K = DMODEL, N = QKVD;
    const int bm = blockIdx.y * 128, bn = blockIdx.x * 128;
    const int tid = threadIdx.x;
    const int wid = tid >> 5, lane = tid & 31;
    const int g = lane >> 2, t = lane & 3;
    const int wm = (wid >> 1) * 32, wn = (wid & 1) * 64;
    const int tsel = lane >> 3, r = lane & 7;

    const uint32_t asB = (uint32_t)__cvta_generic_to_shared(As);
    const uint32_t bsB = (uint32_t)__cvta_generic_to_shared(Bs);

    float acc[2][8][4];
#pragma unroll
    for (int i = 0; i < 2; i++)
#pragma unroll
        for (int j = 0; j < 8; j++)
#pragma unroll
            for (int k = 0; k < 4; k++) acc[i][j][k] = 0.0f;

    auto issue = [&](int stg, int k0) {
#pragma unroll
        for (int i = 0; i < 2; i++) {
            int f = tid + i * 256;
            int row = f >> 2, ch = f & 3;
            cp_async16(asB + (stg * QA_STAGE + row * QA_PITCH) * 2 + ch * 16,
                       &A[(size_t)(bm + row) * K + k0 + ch * 8]);
        }
#pragma unroll
        for (int i = 0; i < 2; i++) {
            int f = tid + i * 256;
            int row = f >> 4, ch = f & 15;
            cp_async16(bsB + (stg * QB_STAGE + row * QB_PITCH) * 2 + ch * 16,
                       &B[(size_t)(k0 + row) * N + bn + ch * 8]);
        }
    };

    const int NIT = K / 32;
    issue(0, 0);
    asm volatile("cp.async.commit_group;");
    issue(1, 32);
    asm volatile("cp.async.commit_group;");

    for (int it = 0; it < NIT; ++it) {
        int cur = it % 3;
        if (it + 2 < NIT) issue((it + 2) % 3, (it + 2) * 32);
        asm volatile("cp.async.commit_group;");
        asm volatile("cp.async.wait_group 2;");
        __syncthreads();

        uint32_t aBase = asB + cur * QA_STAGE * 2;
        uint32_t bBase = bsB + cur * QB_STAGE * 2;
#pragma unroll
        for (int ks = 0; ks < 32; ks += 16) {
            uint32_t aF[2][4];
#pragma unroll
            for (int mt = 0; mt < 2; mt++) {
                int row = wm + mt * 16 + ((tsel & 1) ? 8 : 0) + r;
                int col = ks + ((tsel & 2) ? 8 : 0);
                ldm_x4(aF[mt], aBase + row * (QA_PITCH * 2) + col * 2);
            }
            uint32_t bF[8][2];
#pragma unroll
            for (int p = 0; p < 4; p++) {
                int krow = ks + ((tsel & 1) ? 8 : 0) + r;
                int ncol = wn + p * 16 + ((tsel & 2) ? 8 : 0);
                uint32_t rr[4];
                ldm_x4_t(rr, bBase + krow * (QB_PITCH * 2) + ncol * 2);
                bF[2 * p][0] = rr[0]; bF[2 * p][1] = rr[1];
                bF[2 * p + 1][0] = rr[2]; bF[2 * p + 1][1] = rr[3];
            }
#pragma unroll
            for (int mt = 0; mt < 2; mt++)
#pragma unroll
                for (int nt = 0; nt < 8; nt++)
                    mma_f16(acc[mt][nt], aF[mt], bF[nt], acc[mt][nt]);
        }
        __syncthreads();
    }

#pragma unroll
    for (int mt = 0; mt < 2; mt++) {
        int row = bm + wm + mt * 16 + g;
#pragma unroll
        for (int nt = 0; nt < 8; nt++) {
            int col = bn + wn + nt * 8 + 2 * t;
            float b0 = bias[col], b1 = bias[col + 1];
            float c0 = acc[mt][nt][0] + b0;
            float c1 = acc[mt][nt][1] + b1;
            float c2 = acc[mt][nt][2] + b0;
            float c3 = acc[mt][nt][3] + b1;
            if (col < DMODEL) {
                *(uint32_t*)&Qo[(size_t)row * DMODEL + col] =
                    packf16(c0 * QSCALE, c1 * QSCALE);
                *(uint32_t*)&Qo[(size_t)(row + 8) * DMODEL + col] =
                    packf16(c2 * QSCALE, c3 * QSCALE);
            } else if (col < 2 * DMODEL) {
                int ck = col - DMODEL;
                *(uint32_t*)&Ko[(size_t)row * DMODEL + ck] = packf16(c0, c1);
                *(uint32_t*)&Ko[(size_t)(row + 8) * DMODEL + ck] = packf16(c2, c3);
            } else {
                int cv = col - 2 * DMODEL;
                *(uint32_t*)&Vo[(size_t)row * DMODEL + cv] = packf16(c0, c1);
                *(uint32_t*)&Vo[(size_t)(row + 8) * DMODEL + cv] = packf16(c2, c3);
            }
        }
    }
}

// ---------------------------------------------------------------------------
// Generic fp16 GEMM (FFN), cp.async 3-stage (dynamic smem).
// ---------------------------------------------------------------------------
template<bool RELU, bool OUTHF>
__global__ __launch_bounds__(256)
void gemm_f16(const uint16_t* __restrict__ A, const uint16_t* __restrict__ B,
              const float* __restrict__ bias, float* __restrict__ Cf,
              uint16_t* __restrict__ Cb, int M, int N, int K) {
    extern __shared__ uint16_t dynsmem[];
    uint16_t* As = dynsmem;
    uint16_t* Bs = dynsmem + 3 * QA_STAGE;
    const int bm = blockIdx.y * 128, bn = blockIdx.x * 128;
    const int tid = threadIdx.x;
    const int wid = tid >> 5, lane = tid & 31;
    const int g = lane >> 2, t = lane & 3;
    const int wm = (wid >> 1) * 32, wn = (wid & 1) * 64;
    const int tsel = lane >> 3, r = lane & 7;

    const uint32_t asB = (uint32_t)__cvta_generic_to_shared(As);
    const uint32_t bsB = (uint32_t)__cvta_generic_to_shared(Bs);

    float acc[2][8][4];
#pragma unroll
    for (int i = 0; i < 2; i++)
#pragma unroll
        for (int j = 0; j < 8; j++)
#pragma unroll
            for (int k = 0; k < 4; k++) acc[i][j][k] = 0.0f;

    auto issue = [&](int stg, int k0) {
#pragma unroll
        for (int i = 0; i < 2; i++) {
            int f = tid + i * 256;
            int row = f >> 2, ch = f & 3;
            cp_async16(asB + (stg * QA_STAGE + row * QA_PITCH) * 2 + ch * 16,
                       &A[(size_t)(bm + row) * K + k0 + ch * 8]);
        }
#pragma unroll
        for (int i = 0; i < 2; i++) {
            int f = tid + i * 256;
            int row = f >> 4, ch = f & 15;
            cp_async16(bsB + (stg * QB_STAGE + row * QB_PITCH) * 2 + ch * 16,
                       &B[(size_t)(k0 + row) * N + bn + ch * 8]);
        }
    };

    const int NIT = K / 32;
    issue(0, 0);
    asm volatile("cp.async.commit_group;");
    issue(1, 32);
    asm volatile("cp.async.commit_group;");

    for (int it = 0; it < NIT; ++it) {
        int cur = it % 3;
        if (it + 2 < NIT) issue((it + 2) % 3, (it + 2) * 32);
        asm volatile("cp.async.commit_group;");
        asm volatile("cp.async.wait_group 2;");
        __syncthreads();

        uint32_t aBase = asB + cur * QA_STAGE * 2;
        uint32_t bBase = bsB + cur * QB_STAGE * 2;
#pragma unroll
        for (int ks = 0; ks < 32; ks += 16) {
            uint32_t aF[2][4];
#pragma unroll
            for (int mt = 0; mt < 2; mt++) {
                int row = wm + mt * 16 + ((tsel & 1) ? 8 : 0) + r;
                int col = ks + ((tsel & 2) ? 8 : 0);
                ldm_x4(aF[mt], aBase + row * (QA_PITCH * 2) + col * 2);
            }
            uint32_t bF[8][2];
#pragma unroll
            for (int p = 0; p < 4; p++) {
                int krow = ks + ((tsel & 1) ? 8 : 0) + r;
                int ncol = wn + p * 16 + ((tsel & 2) ? 8 : 0);
                uint32_t rr[4];
                ldm_x4_t(rr, bBase + krow * (QB_PITCH * 2) + ncol * 2);
                bF[2 * p][0] = rr[0]; bF[2 * p][1] = rr[1];
                bF[2 * p + 1][0] = rr[2]; bF[2 * p + 1][1] = rr[3];
            }
#pragma unroll
            for (int mt = 0; mt < 2; mt++)
#pragma unroll
                for (int nt = 0; nt < 8; nt++)
                    mma_f16(acc[mt][nt], aF[mt], bF[nt], acc[mt][nt]);
        }
        __syncthreads();
    }

#pragma unroll
    for (int mt = 0; mt < 2; mt++) {
        int row = bm + wm + mt * 16 + g;
#pragma unroll
        for (int nt = 0; nt < 8; nt++) {
            int col = bn + wn + nt * 8 + 2 * t;
            float b0 = bias[col], b1 = bias[col + 1];
            float c0 = acc[mt][nt][0] + b0;
            float c1 = acc[mt][nt][1] + b1;
            float c2 = acc[mt][nt][2] + b0;
            float c3 = acc[mt][nt][3] + b1;
            if (RELU) {
                c0 = fmaxf(c0, 0.0f); c1 = fmaxf(c1, 0.0f);
                c2 = fmaxf(c2, 0.0f); c3 = fmaxf(c3, 0.0f);
            }
            if (OUTHF) {
                *(uint32_t*)&Cb[(size_t)row * N + col] = packf16(c0, c1);
                *(uint32_t*)&Cb[(size_t)(row + 8) * N + col] = packf16(c2, c3);
            } else {
                *(float2*)&Cf[(size_t)row * N + col] = make_float2(c0, c1);
                *(float2*)&Cf[(size_t)(row + 8) * N + col] = make_float2(c2, c3);
            }
        }
    }
}

// ---------------------------------------------------------------------------
// FlashAttention (R10 core, best measured): 64 q-rows/block, fp16 QK^T with
// f16 acc, fused SMAX+mask, ex2.f16x2, f32 PV acc, 2-stage cp.async K/V.
// ---------------------------------------------------------------------------
#define TPITCH 72
#define TSTAGE (64*TPITCH)
#define ATTN_SMEM (2*TSTAGE*2*2)   // 36864 B

__global__ __launch_bounds__(128)
void attn_kernel(const uint16_t* __restrict__ Qm, const uint16_t* __restrict__ Km,
                 const uint16_t* __restrict__ Vm,
                 const unsigned int* __restrict__ maskbits,
                 float* __restrict__ out) {
    extern __shared__ uint16_t dynsmem[];
    uint16_t* Ks = dynsmem;
    uint16_t* Vs = dynsmem + 2 * TSTAGE;

    const int qt = blockIdx.x;
    const int bh = blockIdx.y;
    const int b = bh >> 3, h = bh & 7;
    const int tid = threadIdx.x;
    const int wid = tid >> 5, lane = tid & 31;
    const int g = lane >> 2, t = lane & 3;
    const int tsel = lane >> 3, r = lane & 7;
    const int r0 = wid * 16;

    const int qrow_lo = qt * 64 + r0 + g;
    const size_t growL = (size_t)b * SEQ + qrow_lo;

    const uint32_t ksB = (uint32_t)__cvta_generic_to_shared(Ks);
    const uint32_t vsB = (uint32_t)__cvta_generic_to_shared(Vs);

    uint32_t qa[4][4];
    {
        const uint16_t* qb = Qm + growL * DMODEL + h * HDIM;
#pragma unroll
        for (int ks = 0; ks < 4; ks++) {
            qa[ks][0] = *(const uint32_t*)(qb + ks * 16 + 2 * t);
            qa[ks][1] = *(const uint32_t*)(qb + 8 * DMODEL + ks * 16 + 2 * t);
            qa[ks][2] = *(const uint32_t*)(qb + ks * 16 + 8 + 2 * t);
            qa[ks][3] = *(const uint32_t*)(qb + 8 * DMODEL + ks * 16 + 8 + 2 * t);
        }
    }

    float o[8][4];
#pragma unroll
    for (int j = 0; j < 8; j++)
#pragma unroll
        for (int k = 0; k < 4; k++) o[j][k] = 0.0f;
    float l_lo = 0.0f, l_hi = 0.0f;

    const unsigned int* mbL = maskbits + growL * (SEQ / 32);
    const unsigned int* mbH = mbL + 8 * (SEQ / 32);

    auto issue = [&](int stg, int kt) {
        const size_t rowbase = (size_t)b * SEQ + kt * 64;
#pragma unroll
        for (int i = 0; i < 4; i++) {
            int f = tid + i * 128;
            int row = f >> 3, ch = f & 7;
            size_t src = (rowbase + row) * DMODEL + h * HDIM + ch * 8;
            cp_async16(ksB + (stg * TSTAGE + row * TPITCH) * 2 + ch * 16, &Km[src]);
            cp_async16(vsB + (stg * TSTAGE + row * TPITCH) * 2 + ch * 16, &Vm[src]);
        }
    };

    issue(0, 0);
    asm volatile("cp.async.commit_group;");

    const int NKT = SEQ / 64;
    for (int kt = 0; kt < NKT; kt++) {
        if (kt + 1 < NKT) issue((kt + 1) & 1, kt + 1);
        asm volatile("cp.async.commit_group;");
        asm volatile("cp.async.wait_group 1;");
        __syncthreads();

        const uint32_t kBase = ksB + (kt & 1) * TSTAGE * 2;
        const uint32_t vBase = vsB + (kt & 1) * TSTAGE * 2;

        // S = Q K^T, f16 accumulators
        uint32_t S16[8][2];
#pragma unroll
        for (int j = 0; j < 8; j++) { S16[j][0] = 0; S16[j][1] = 0; }
#pragma unroll
        for (int ks = 0; ks < 4; ks++) {
            uint32_t bK[8][2];
#pragma unroll
            for (int p = 0; p < 4; p++) {
                int key = p * 16 + ((tsel & 2) ? 8 : 0) + r;
                int d = ks * 16 + ((tsel & 1) ? 8 : 0);
                uint32_t rr[4];
                ldm_x4(rr, kBase + key * (TPITCH * 2) + d * 2);
                bK[2 * p][0] = rr[0]; bK[2 * p][1] = rr[1];
                bK[2 * p + 1][0] = rr[2]; bK[2 * p + 1][1] = rr[3];
            }
#pragma unroll
            for (int j = 0; j < 8; j++)
                mma_f16c16(S16[j], qa[ks], bK[j]);
        }

        // Fused SMAX + mask subtract, ex2 -> P (A-frag layout)
        {
            unsigned w0L = mbL[kt * 2], w1L = mbL[kt * 2 + 1];
            unsigned w0H = mbH[kt * 2], w1H = mbH[kt * 2 + 1];
            const int sh = 2 * t;
            auto squash = [&](unsigned w) {
                unsigned x = (w >> sh) & 0x03030303u;
                x |= x >> 4;
                x &= 0x00330033u;
                x |= x >> 8;
                return x & 0xFFFFu;
            };
            unsigned mfL = squash(w0L) | (squash(w1L) << 16);
            unsigned mfH = squash(w0H) | (squash(w1H) << 16);
            uint32_t suml = 0, sumh = 0;
#pragma unroll
            for (int j = 0; j < 8; j++) {
                unsigned fL = mfL >> (4 * j), fH = mfH >> (4 * j);
                uint32_t mw0 = ((fL & 1u) ? 0x7BFFu : 0x4400u)
                             | ((fL & 2u) ? 0x7BFF0000u : 0x44000000u);
                uint32_t mw1 = ((fH & 1u) ? 0x7BFFu : 0x4400u)
                             | ((fH & 2u) ? 0x7BFF0000u : 0x44000000u);
                asm("sub.f16x2 %0, %0, %1;" : "+r"(S16[j][0]) : "r"(mw0));
                asm("sub.f16x2 %0, %0, %1;" : "+r"(S16[j][1]) : "r"(mw1));
                asm("ex2.approx.f16x2 %0, %0;" : "+r"(S16[j][0]));
                asm("ex2.approx.f16x2 %0, %0;" : "+r"(S16[j][1]));
                asm("add.f16x2 %0, %0, %1;" : "+r"(suml) : "r"(S16[j][0]));
                asm("add.f16x2 %0, %0, %1;" : "+r"(sumh) : "r"(S16[j][1]));
            }
            __half2 hl = *reinterpret_cast<__half2*>(&suml);
            __half2 hh = *reinterpret_cast<__half2*>(&sumh);
            l_lo += __low2float(hl) + __high2float(hl);
            l_hi += __low2float(hh) + __high2float(hh);
        }

        // O += P V  (f32 accumulators)
#pragma unroll
        for (int ks = 0; ks < 4; ks++) {
            uint32_t pa[4] = {S16[2*ks][0], S16[2*ks][1],
                              S16[2*ks+1][0], S16[2*ks+1][1]};
            uint32_t bV[8][2];
#pragma unroll
            for (int p = 0; p < 4; p++) {
                int key = ks * 16 + ((tsel & 1) ? 8 : 0) + r;
                int d = p * 16 + ((tsel & 2) ? 8 : 0);
                uint32_t rr[4];
                ldm_x4_t(rr, vBase + key * (TPITCH * 2) + d * 2);
                bV[2 * p][0] = rr[0]; bV[2 * p][1] = rr[1];
                bV[2 * p + 1][0] = rr[2]; bV[2 * p + 1][1] = rr[3];
            }
#pragma unroll
            for (int j = 0; j < 8; j++)
                mma_f16(o[j], pa, bV[j], o[j]);
        }
        __syncthreads();
    }

    // Final cross-lane l reduction
    l_lo += __shfl_xor_sync(0xffffffffu, l_lo, 1, 4);
    l_lo += __shfl_xor_sync(0xffffffffu, l_lo, 2, 4);
    l_hi += __shfl_xor_sync(0xffffffffu, l_hi, 1, 4);
    l_hi += __shfl_xor_sync(0xffffffffu, l_hi, 2, 4);

    const float inv_lo = 1.0f / l_lo;
    const float inv_hi = 1.0f / l_hi;
    float* obase = out + growL * DMODEL + h * HDIM;
#pragma unroll
    for (int j = 0; j < 8; j++) {
        int col = j * 8 + 2 * t;
        *(float2*)(obase + col) =
            make_float2(o[j][0] * inv_lo, o[j][1] * inv_lo);
        *(float2*)(obase + 8 * DMODEL + col) =
            make_float2(o[j][2] * inv_hi, o[j][3] * inv_hi);
    }
}

// ---------------------------------------------------------------------------
// Residual + LayerNorm; DUAL also writes fp16 copy
// ---------------------------------------------------------------------------
template<bool DUAL>
__global__ __launch_bounds__(128)
void ln_kernel(const float* __restrict__ a, const float* __restrict__ bb,
               const float* __restrict__ gamma, const float* __restrict__ beta,
               float* __restrict__ out, uint16_t* __restrict__ out_b) {
    __shared__ float red[4];
    const int row = blockIdx.x;
    const int tid = threadIdx.x;
    const size_t base = (size_t)row * DMODEL + tid * 4;

    float4 av = *(const float4*)(a + base);
    float4 bv = *(const float4*)(bb + base);
    float x0 = av.x + bv.x, x1 = av.y + bv.y;
    float x2 = av.z + bv.z, x3 = av.w + bv.w;

    float sum = x0 + x1 + x2 + x3;
#pragma unroll
    for (int o = 16; o; o >>= 1) sum += __shfl_xor_sync(0xffffffffu, sum, o);
    if ((tid & 31) == 0) red[tid >> 5] = sum;
    __syncthreads();
    float mean = (red[0] + red[1] + red[2] + red[3]) * (1.0f / DMODEL);
    __syncthreads();

    float d0 = x0 - mean, d1 = x1 - mean, d2 = x2 - mean, d3 = x3 - mean;
    float sq = d0 * d0 + d1 * d1 + d2 * d2 + d3 * d3;
#pragma unroll
    for (int o = 16; o; o >>= 1) sq += __shfl_xor_sync(0xffffffffu, sq, o);
    if ((tid & 31) == 0) red[tid >> 5] = sq;
    __syncthreads();
    float var = (red[0] + red[1] + red[2] + red[3]) * (1.0f / DMODEL);
    float rs = rsqrtf(var + 1e-5f);

    float4 gv = *(const float4*)(gamma + tid * 4);
    float4 be = *(const float4*)(beta + tid * 4);
    float y0 = d0 * rs * gv.x + be.x;
    float y1 = d1 * rs * gv.y + be.y;
    float y2 = d2 * rs * gv.z + be.z;
    float y3 = d3 * rs * gv.w + be.w;
    *(float4*)(out + base) = make_float4(y0, y1, y2, y3);
    if (DUAL) {
        ((uint2*)out_b)[base / 4] =
            make_uint2(packf16(y0, y1), packf16(y2, y3));
    }
}

// ---------------------------------------------------------------------------
// Launch: fork mask + w1/w2 conversion onto a side stream, join before use.
// Streams/events are function-local statics (constant infra, no per-call
// behavior change; creation is capture-legal).
// ---------------------------------------------------------------------------
extern "C" void kernel_launch(void* const* d_in, const int* in_sizes, int n_in,
                              void* d_out, int out_size) {
    const float* edge_x    = (const float*)d_in[0];
    const void*  edge_mask =               d_in[1];
    const float* Wqkv      = (const float*)d_in[2];
    const float* bqkv      = (const float*)d_in[3];
    const float* W1        = (const float*)d_in[4];
    const float* b1        = (const float*)d_in[5];
    const float* W2        = (const float*)d_in[6];
    const float* b2        = (const float*)d_in[7];
    const float* gamma1    = (const float*)d_in[8];
    const float* beta1     = (const float*)d_in[9];
    const float* gamma2    = (const float*)d_in[10];
    const float* beta2     = (const float*)d_in[11];
    float* out = (float*)d_out;

    float *attnout, *x1, *ff2;
    uint16_t *qb, *kb, *vb, *xb, *wqkvb, *w1b, *w2b, *x1b, *ffb;
    unsigned int* maskbits;
    cudaGetSymbolAddress((void**)&qb,       g_q);
    cudaGetSymbolAddress((void**)&kb,       g_k);
    cudaGetSymbolAddress((void**)&vb,       g_v);
    cudaGetSymbolAddress((void**)&xb,       g_xb);
    cudaGetSymbolAddress((void**)&wqkvb,    g_wqkvb);
    cudaGetSymbolAddress((void**)&w1b,      g_w1b);
    cudaGetSymbolAddress((void**)&w2b,      g_w2b);
    cudaGetSymbolAddress((void**)&attnout,  g_attnout);
    cudaGetSymbolAddress((void**)&x1,       g_x1);
    cudaGetSymbolAddress((void**)&x1b,      g_x1b);
    cudaGetSymbolAddress((void**)&ffb,      g_ffb);
    cudaGetSymbolAddress((void**)&ff2,      g_ff2);
    cudaGetSymbolAddress((void**)&maskbits, g_maskbits);

    cudaFuncSetAttribute(gemm_qkv_f16,
                         cudaFuncAttributeMaxDynamicSharedMemorySize, GEMM_SMEM);
    cudaFuncSetAttribute(gemm_f16<true, true>,
                         cudaFuncAttributeMaxDynamicSharedMemorySize, GEMM_SMEM);
    cudaFuncSetAttribute(gemm_f16<false, false>,
                         cudaFuncAttributeMaxDynamicSharedMemorySize, GEMM_SMEM);
    cudaFuncSetAttribute(attn_kernel,
                         cudaFuncAttributeMaxDynamicSharedMemorySize, ATTN_SMEM);

    static cudaStream_t s_side = nullptr;
    static cudaEvent_t  e_fork = nullptr, e_mask = nullptr, e_w12 = nullptr;
    if (s_side == nullptr) {
        cudaStreamCreateWithFlags(&s_side, cudaStreamNonBlocking);
        cudaEventCreateWithFlags(&e_fork, cudaEventDisableTiming);
        cudaEventCreateWithFlags(&e_mask, cudaEventDisableTiming);
        cudaEventCreateWithFlags(&e_w12,  cudaEventDisableTiming);
    }

    // Fork: side stream runs mask + w1/w2 conversion
    cudaEventRecord(e_fork, 0);
    cudaStreamWaitEvent(s_side, e_fork, 0);
    mask_kernel<<<2048, 256, 0, s_side>>>(edge_mask, maskbits, BSZ * SEQ * SEQ);
    cudaEventRecord(e_mask, s_side);
    convert_w12_kernel<<<512, 256, 0, s_side>>>(W1, W2, w1b, w2b);
    cudaEventRecord(e_w12, s_side);

    // Main stream: x/wqkv conversion -> QKV GEMM
    convert_main_kernel<<<2432, 256>>>(edge_x, Wqkv, xb, wqkvb);
    gemm_qkv_f16<<<dim3(QKVD / 128, NROWS / 128), 256, GEMM_SMEM>>>(
        xb, wqkvb, bqkv, qb, kb, vb);

    // Join mask before attention
    cudaStreamWaitEvent(0, e_mask, 0);
    attn_kernel<<<dim3(SEQ / 64, BSZ * NHEAD), 128, ATTN_SMEM>>>(
        qb, kb, vb, maskbits, attnout);

    ln_kernel<true><<<NROWS, 128>>>(edge_x, attnout, gamma1, beta1, x1, x1b);

    // Join w1/w2 conversion before the FFN GEMMs
    cudaStreamWaitEvent(0, e_w12, 0);
    gemm_f16<true, true><<<dim3(DMODEL / 128, NROWS / 128), 256, GEMM_SMEM>>>(
        x1b, w1b, b1, nullptr, ffb, NROWS, DMODEL, DMODEL);

    gemm_f16<false, false><<<dim3(DMODEL / 128, NROWS / 128), 256, GEMM_SMEM>>>(
        ffb, w2b, b2, ff2, nullptr, NROWS, DMODEL, DMODEL);

    ln_kernel<false><<<NROWS, 128>>>(x1, ff2, gamma2, beta2, out, nullptr);
}

// round 16
// speedup vs baseline: 1.0265x; 1.0116x over previous
#include <cuda_runtime.h>
#include <cuda_fp16.h>
#include <cstdint>

#define BSZ    8
#define SEQ    1024
#define DMODEL 512
#define NHEAD  8
#define HDIM   64
#define NROWS  (BSZ*SEQ)
#define QKVD   (3*DMODEL)

// Q pre-scale: hd^-0.5 * log2(e)  (scores in log2 domain)
#define QSCALE 0.1803368801111204f

// ---------------------------------------------------------------------------
// Scratch
// ---------------------------------------------------------------------------
__device__ uint16_t g_q      [NROWS * DMODEL];
__device__ uint16_t g_k      [NROWS * DMODEL];
__device__ uint16_t g_v      [NROWS * DMODEL];
__device__ uint16_t g_xb     [NROWS * DMODEL];
__device__ uint16_t g_wqkvb  [DMODEL * QKVD];
__device__ uint16_t g_w1b    [DMODEL * DMODEL];
__device__ uint16_t g_w2b    [DMODEL * DMODEL];
__device__ float    g_attnout[NROWS * DMODEL];
__device__ float    g_x1     [NROWS * DMODEL];
__device__ uint16_t g_x1b    [NROWS * DMODEL];
__device__ uint16_t g_ffb    [NROWS * DMODEL];
__device__ float    g_ff2    [NROWS * DMODEL];
__device__ unsigned g_maskbits[NROWS * (SEQ/32)];

// ---------------------------------------------------------------------------
// helpers
// ---------------------------------------------------------------------------
__device__ __forceinline__ uint32_t packf16(float lo, float hi) {
    uint32_t r;
    asm("cvt.rn.f16x2.f32 %0, %1, %2;" : "=r"(r) : "f"(hi), "f"(lo));
    return r;
}
__device__ __forceinline__ void mma_f16(float d[4], const uint32_t a[4],
                                        const uint32_t b[2], const float c[4]) {
    asm volatile(
        "mma.sync.aligned.m16n8k16.row.col.f32.f16.f16.f32 "
        "{%0,%1,%2,%3}, {%4,%5,%6,%7}, {%8,%9}, {%10,%11,%12,%13};"
        : "=f"(d[0]), "=f"(d[1]), "=f"(d[2]), "=f"(d[3])
        : "r"(a[0]), "r"(a[1]), "r"(a[2]), "r"(a[3]), "r"(b[0]), "r"(b[1]),
          "f"(c[0]), "f"(c[1]), "f"(c[2]), "f"(c[3]));
}
// f16-accumulator variant (2x tensor rate; C/D are 2 packed f16x2 regs)
__device__ __forceinline__ void mma_f16c16(uint32_t d[2], const uint32_t a[4],
                                           const uint32_t b[2]) {
    asm volatile(
        "mma.sync.aligned.m16n8k16.row.col.f16.f16.f16.f16 "
        "{%0,%1}, {%2,%3,%4,%5}, {%6,%7}, {%0,%1};"
        : "+r"(d[0]), "+r"(d[1])
        : "r"(a[0]), "r"(a[1]), "r"(a[2]), "r"(a[3]), "r"(b[0]), "r"(b[1]));
}
__device__ __forceinline__ void cp_async16(uint32_t dst, const void* src) {
    asm volatile("cp.async.cg.shared.global [%0], [%1], 16;"
                 :: "r"(dst), "l"(src));
}
__device__ __forceinline__ void ldm_x4(uint32_t r[4], uint32_t addr) {
    asm volatile("ldmatrix.sync.aligned.m8n8.x4.shared.b16 {%0,%1,%2,%3}, [%4];"
                 : "=r"(r[0]), "=r"(r[1]), "=r"(r[2]), "=r"(r[3]) : "r"(addr));
}
__device__ __forceinline__ void ldm_x4_t(uint32_t r[4], uint32_t addr) {
    asm volatile("ldmatrix.sync.aligned.m8n8.x4.trans.shared.b16 {%0,%1,%2,%3}, [%4];"
                 : "=r"(r[0]), "=r"(r[1]), "=r"(r[2]), "=r"(r[3]) : "r"(addr));
}

// ---------------------------------------------------------------------------
// Mask: per-block dtype detection + vectorized bit expansion
// ---------------------------------------------------------------------------
__global__ __launch_bounds__(256)
void mask_kernel(const void* __restrict__ m, unsigned* __restrict__ out, int n) {
    __shared__ int s3f, soff;
    if (threadIdx.x == 0) { s3f = 0; soff = 0; }
    __syncthreads();
    {
        uint4 v = ((const uint4*)m)[threadIdx.x];
        unsigned w[4] = {v.x, v.y, v.z, v.w};
        int l3f = 0, loff = 0;
#pragma unroll
        for (int j = 0; j < 4; j++) {
            unsigned x = w[j];
            if (((x & 0xFF) == 0x3F) || (((x >> 8) & 0xFF) == 0x3F) ||
                (((x >> 16) & 0xFF) == 0x3F) || (((x >> 24) & 0xFF) == 0x3F))
                l3f++;
            if (x & 0xFFFFFF00u) loff++;
        }
        if (l3f) atomicAdd(&s3f, 1);
        if (loff) atomicAdd(&soff, 1);
    }
    __syncthreads();
    const int kind = (s3f > 0) ? 2 : ((soff > 0) ? 0 : 1);

    const int nthreads = gridDim.x * blockDim.x;
    const int nchunk = n / 16;
    for (int idx = blockIdx.x * blockDim.x + threadIdx.x; idx < nchunk;
         idx += nthreads) {
        unsigned bits = 0;
        if (kind == 0) {
            uint4 v = ((const uint4*)m)[idx];
            unsigned w[4] = {v.x, v.y, v.z, v.w};
#pragma unroll
            for (int j = 0; j < 4; j++)
#pragma unroll
                for (int bpos = 0; bpos < 4; bpos++)
                    if ((w[j] >> (8 * bpos)) & 0xFFu)
                        bits |= 1u << (j * 4 + bpos);
        } else {
            const uint4* p = (const uint4*)m + idx * 4;
#pragma unroll
            for (int j = 0; j < 4; j++) {
                uint4 v = p[j];
                if (v.x) bits |= 1u << (j * 4 + 0);
                if (v.y) bits |= 1u << (j * 4 + 1);
                if (v.z) bits |= 1u << (j * 4 + 2);
                if (v.w) bits |= 1u << (j * 4 + 3);
            }
        }
        unsigned other = __shfl_xor_sync(0xffffffffu, bits, 1);
        if ((threadIdx.x & 1) == 0)
            out[idx >> 1] = bits | (other << 16);
    }
}

// ---------------------------------------------------------------------------
// Conversions -> fp16
// ---------------------------------------------------------------------------
#define NX4 (NROWS*DMODEL/4)
#define NW4 (DMODEL*QKVD/4)
#define NF4 (DMODEL*DMODEL/4)

__global__ __launch_bounds__(256)
void convert_main_kernel(const float* __restrict__ x,
                         const float* __restrict__ wqkv,
                         uint16_t* __restrict__ xb,
                         uint16_t* __restrict__ wqkvb) {
    const int total = NX4 + NW4;
    const int stride = gridDim.x * blockDim.x;
    for (int i = blockIdx.x * blockDim.x + threadIdx.x; i < total; i += stride) {
        const float4* src;
        uint2* dst;
        int j;
        if (i < NX4) { j = i;       src = (const float4*)x    + j; dst = (uint2*)xb    + j; }
        else         { j = i - NX4; src = (const float4*)wqkv + j; dst = (uint2*)wqkvb + j; }
        float4 v = *src;
        *dst = make_uint2(packf16(v.x, v.y), packf16(v.z, v.w));
    }
}

__global__ __launch_bounds__(256)
void convert_w12_kernel(const float* __restrict__ w1, const float* __restrict__ w2,
                        uint16_t* __restrict__ w1b, uint16_t* __restrict__ w2b) {
    const int total = 2 * NF4;
    const int stride = gridDim.x * blockDim.x;
    for (int i = blockIdx.x * blockDim.x + threadIdx.x; i < total; i += stride) {
        const float4* src;
        uint2* dst;
        int j;
        if (i < NF4) { j = i;       src = (const float4*)w1 + j; dst = (uint2*)w1b + j; }
        else         { j = i - NF4; src = (const float4*)w2 + j; dst = (uint2*)w2b + j; }
        float4 v = *src;
        *dst = make_uint2(packf16(v.x, v.y), packf16(v.z, v.w));
    }
}

// ---------------------------------------------------------------------------
// QKV GEMM, fp16 with f16 ACCUMULATORS (2x tensor rate, half the acc regs),
// cp.async 3-stage (dynamic smem), ldmatrix.
// ---------------------------------------------------------------------------
#define QA_PITCH 40
#define QB_PITCH 136
#define QA_STAGE (128*QA_PITCH)
#define QB_STAGE (32*QB_PITCH)
#define GEMM_SMEM (3*(QA_STAGE+QB_STAGE)*2)

__global__ __launch_bounds__(256)
void gemm_qkv_f16(const uint16_t* __restrict__ A, const uint16_t* __restrict__ B,
                  const float* __restrict__ bias,
                  uint16_t* __restrict__ Qo, uint16_t* __restrict__ Ko,
                  uint16_t* __restrict__ Vo) {
    extern __shared__ uint16_t dynsmem[];
    uint16_t* As = dynsmem;
    uint16_t* Bs = dynsmem + 3 * QA_STAGE;
    const int K = DMODEL, N = QKVD;
    const int bm = blockIdx.y * 128, bn = blockIdx.x * 128;
    const int tid = threadIdx.x;
    const int wid = tid >> 5, lane = tid & 31;
    const int g = lane >> 2, t = lane & 3;
    const int wm = (wid >> 1) * 32, wn = (wid & 1) * 64;
    const int tsel = lane >> 3, r = lane & 7;

    const uint32_t asB = (uint32_t)__cvta_generic_to_shared(As);
    const uint32_t bsB = (uint32_t)__cvta_generic_to_shared(Bs);

    // Packed f16 accumulators: acc16[mt][nt][0] = (row g,  cols 2t,2t+1)
    //                          acc16[mt][nt][1] = (row g+8, cols 2t,2t+1)
    uint32_t acc16[2][8][2];
#pragma unroll
    for (int i = 0; i < 2; i++)
#pragma unroll
        for (int j = 0; j < 8; j++) { acc16[i][j][0] = 0; acc16[i][j][1] = 0; }

    auto issue = [&](int stg, int k0) {
#pragma unroll
        for (int i = 0; i < 2; i++) {
            int f = tid + i * 256;
            int row = f >> 2, ch = f & 3;
            cp_async16(asB + (stg * QA_STAGE + row * QA_PITCH) * 2 + ch * 16,
                       &A[(size_t)(bm + row) * K + k0 + ch * 8]);
        }
#pragma unroll
        for (int i = 0; i < 2; i++) {
            int f = tid + i * 256;
            int row = f >> 4, ch = f & 15;
            cp_async16(bsB + (stg * QB_STAGE + row * QB_PITCH) * 2 + ch * 16,
                       &B[(size_t)(k0 + row) * N + bn + ch * 8]);
        }
    };

    const int NIT = K / 32;
    issue(0, 0);
    asm volatile("cp.async.commit_group;");
    issue(1, 32);
    asm volatile("cp.async.commit_group;");

    for (int it = 0; it < NIT; ++it) {
        int cur = it % 3;
        if (it + 2 < NIT) issue((it + 2) % 3, (it + 2) * 32);
        asm volatile("cp.async.commit_group;");
        asm volatile("cp.async.wait_group 2;");
        __syncthreads();

        uint32_t aBase = asB + cur * QA_STAGE * 2;
        uint32_t bBase = bsB + cur * QB_STAGE * 2;
#pragma unroll
        for (int ks = 0; ks < 32; ks += 16) {
            uint32_t aF[2][4];
#pragma unroll
            for (int mt = 0; mt < 2; mt++) {
                int row = wm + mt * 16 + ((tsel & 1) ? 8 : 0) + r;
                int col = ks + ((tsel & 2) ? 8 : 0);
                ldm_x4(aF[mt], aBase + row * (QA_PITCH * 2) + col * 2);
            }
            uint32_t bF[8][2];
#pragma unroll
            for (int p = 0; p < 4; p++) {
                int krow = ks + ((tsel & 1) ? 8 : 0) + r;
                int ncol = wn + p * 16 + ((tsel & 2) ? 8 : 0);
                uint32_t rr[4];
                ldm_x4_t(rr, bBase + krow * (QB_PITCH * 2) + ncol * 2);
                bF[2 * p][0] = rr[0]; bF[2 * p][1] = rr[1];
                bF[2 * p + 1][0] = rr[2]; bF[2 * p + 1][1] = rr[3];
            }
#pragma unroll
            for (int mt = 0; mt < 2; mt++)
#pragma unroll
                for (int nt = 0; nt < 8; nt++)
                    mma_f16c16(acc16[mt][nt], aF[mt], bF[nt]);
        }
        __syncthreads();
    }

    // Epilogue: unpack f16 pairs, add bias in f32, route Q/K/V
#pragma unroll
    for (int mt = 0; mt < 2; mt++) {
        int row = bm + wm + mt * 16 + g;
#pragma unroll
        for (int nt = 0; nt < 8; nt++) {
            int col = bn + wn + nt * 8 + 2 * t;
            float b0 = bias[col], b1 = bias[col + 1];
            __half2 lo2 = *reinterpret_cast<__half2*>(&acc16[mt][nt][0]);
            __half2 hi2 = *reinterpret_cast<__half2*>(&acc16[mt][nt][1]);
            float c0 = __low2float(lo2) + b0;
            float c1 = __high2float(lo2) + b1;
            float c2 = __low2float(hi2) + b0;
            float c3 = __high2float(hi2) + b1;
            if (col < DMODEL) {
                *(uint32_t*)&Qo[(size_t)row * DMODEL + col] =
                    packf16(c0 * QSCALE, c1 * QSCALE);
                *(uint32_t*)&Qo[(size_t)(row + 8) * DMODEL + col] =
                    packf16(c2 * QSCALE, c3 * QSCALE);
            } else if (col < 2 * DMODEL) {
                int ck = col - DMODEL;
                *(uint32_t*)&Ko[(size_t)row * DMODEL + ck] = packf16(c0, c1);
                *(uint32_t*)&Ko[(size_t)(row + 8) * DMODEL + ck] = packf16(c2, c3);
            } else {
                int cv = col - 2 * DMODEL;
                *(uint32_t*)&Vo[(size_t)row * DMODEL + cv] = packf16(c0, c1);
                *(uint32_t*)&Vo[(size_t)(row + 8) * DMODEL + cv] = packf16(c2, c3);
            }
        }
    }
}

// ---------------------------------------------------------------------------
// Generic fp16 GEMM (FFN), f32 accumulators (precision), cp.async 3-stage.
// ---------------------------------------------------------------------------
template<bool RELU, bool OUTHF>
__global__ __launch_bounds__(256)
void gemm_f16(const uint16_t* __restrict__ A, const uint16_t* __restrict__ B,
              const float* __restrict__ bias, float* __restrict__ Cf,
              uint16_t* __restrict__ Cb, int M, int N, int K) {
    extern __shared__ uint16_t dynsmem[];
    uint16_t* As = dynsmem;
    uint16_t* Bs = dynsmem + 3 * QA_STAGE;
    const int bm = blockIdx.y * 128, bn = blockIdx.x * 128;
    const int tid = threadIdx.x;
    const int wid = tid >> 5, lane = tid & 31;
    const int g = lane >> 2, t = lane & 3;
    const int wm = (wid >> 1) * 32, wn = (wid & 1) * 64;
    const int tsel = lane >> 3, r = lane & 7;

    const uint32_t asB = (uint32_t)__cvta_generic_to_shared(As);
    const uint32_t bsB = (uint32_t)__cvta_generic_to_shared(Bs);

    float acc[2][8][4];
#pragma unroll
    for (int i = 0; i < 2; i++)
#pragma unroll
        for (int j = 0; j < 8; j++)
#pragma unroll
            for (int k = 0; k < 4; k++) acc[i][j][k] = 0.0f;

    auto issue = [&](int stg, int k0) {
#pragma unroll
        for (int i = 0; i < 2; i++) {
            int f = tid + i * 256;
            int row = f >> 2, ch = f & 3;
            cp_async16(asB + (stg * QA_STAGE + row * QA_PITCH) * 2 + ch * 16,
                       &A[(size_t)(bm + row) * K + k0 + ch * 8]);
        }
#pragma unroll
        for (int i = 0; i < 2; i++) {
            int f = tid + i * 256;
            int row = f >> 4, ch = f & 15;
            cp_async16(bsB + (stg * QB_STAGE + row * QB_PITCH) * 2 + ch * 16,
                       &B[(size_t)(k0 + row) * N + bn + ch * 8]);
        }
    };

    const int NIT = K / 32;
    issue(0, 0);
    asm volatile("cp.async.commit_group;");
    issue(1, 32);
    asm volatile("cp.async.commit_group;");

    for (int it = 0; it < NIT; ++it) {
        int cur = it % 3;
        if (it + 2 < NIT) issue((it + 2) % 3, (it + 2) * 32);
        asm volatile("cp.async.commit_group;");
        asm volatile("cp.async.wait_group 2;");
        __syncthreads();

        uint32_t aBase = asB + cur * QA_STAGE * 2;
        uint32_t bBase = bsB + cur * QB_STAGE * 2;
#pragma unroll
        for (int ks = 0; ks < 32; ks += 16) {
            uint32_t aF[2][4];
#pragma unroll
            for (int mt = 0; mt < 2; mt++) {
                int row = wm + mt * 16 + ((tsel & 1) ? 8 : 0) + r;
                int col = ks + ((tsel & 2) ? 8 : 0);
                ldm_x4(aF[mt], aBase + row * (QA_PITCH * 2) + col * 2);
            }
            uint32_t bF[8][2];
#pragma unroll
            for (int p = 0; p < 4; p++) {
                int krow = ks + ((tsel & 1) ? 8 : 0) + r;
                int ncol = wn + p * 16 + ((tsel & 2) ? 8 : 0);
                uint32_t rr[4];
                ldm_x4_t(rr, bBase + krow * (QB_PITCH * 2) + ncol * 2);
                bF[2 * p][0] = rr[0]; bF[2 * p][1] = rr[1];
                bF[2 * p + 1][0] = rr[2]; bF[2 * p + 1][1] = rr[3];
            }
#pragma unroll
            for (int mt = 0; mt < 2; mt++)
#pragma unroll
                for (int nt = 0; nt < 8; nt++)
                    mma_f16(acc[mt][nt], aF[mt], bF[nt], acc[mt][nt]);
        }
        __syncthreads();
    }

#pragma unroll
    for (int mt = 0; mt < 2; mt++) {
        int row = bm + wm + mt * 16 + g;
#pragma unroll
        for (int nt = 0; nt < 8; nt++) {
            int col = bn + wn + nt * 8 + 2 * t;
            float b0 = bias[col], b1 = bias[col + 1];
            float c0 = acc[mt][nt][0] + b0;
            float c1 = acc[mt][nt][1] + b1;
            float c2 = acc[mt][nt][2] + b0;
            float c3 = acc[mt][nt][3] + b1;
            if (RELU) {
                c0 = fmaxf(c0, 0.0f); c1 = fmaxf(c1, 0.0f);
                c2 = fmaxf(c2, 0.0f); c3 = fmaxf(c3, 0.0f);
            }
            if (OUTHF) {
                *(uint32_t*)&Cb[(size_t)row * N + col] = packf16(c0, c1);
                *(uint32_t*)&Cb[(size_t)(row + 8) * N + col] = packf16(c2, c3);
            } else {
                *(float2*)&Cf[(size_t)row * N + col] = make_float2(c0, c1);
                *(float2*)&Cf[(size_t)(row + 8) * N + col] = make_float2(c2, c3);
            }
        }
    }
}

// ---------------------------------------------------------------------------
// FlashAttention (R10 core, best measured): 64 q-rows/block, fp16 QK^T with
// f16 acc, fused SMAX+mask, ex2.f16x2, f32 PV acc, 2-stage cp.async K/V.
// ---------------------------------------------------------------------------
#define TPITCH 72
#define TSTAGE (64*TPITCH)
#define ATTN_SMEM (2*TSTAGE*2*2)   // 36864 B

__global__ __launch_bounds__(128)
void attn_kernel(const uint16_t* __restrict__ Qm, const uint16_t* __restrict__ Km,
                 const uint16_t* __restrict__ Vm,
                 const unsigned int* __restrict__ maskbits,
                 float* __restrict__ out) {
    extern __shared__ uint16_t dynsmem[];
    uint16_t* Ks = dynsmem;
    uint16_t* Vs = dynsmem + 2 * TSTAGE;

    const int qt = blockIdx.x;
    const int bh = blockIdx.y;
    const int b = bh >> 3, h = bh & 7;
    const int tid = threadIdx.x;
    const int wid = tid >> 5, lane = tid & 31;
    const int g = lane >> 2, t = lane & 3;
    const int tsel = lane >> 3, r = lane & 7;
    const int r0 = wid * 16;

    const int qrow_lo = qt * 64 + r0 + g;
    const size_t growL = (size_t)b * SEQ + qrow_lo;

    const uint32_t ksB = (uint32_t)__cvta_generic_to_shared(Ks);
    const uint32_t vsB = (uint32_t)__cvta_generic_to_shared(Vs);

    uint32_t qa[4][4];
    {
        const uint16_t* qb = Qm + growL * DMODEL + h * HDIM;
#pragma unroll
        for (int ks = 0; ks < 4; ks++) {
            qa[ks][0] = *(const uint32_t*)(qb + ks * 16 + 2 * t);
            qa[ks][1] = *(const uint32_t*)(qb + 8 * DMODEL + ks * 16 + 2 * t);
            qa[ks][2] = *(const uint32_t*)(qb + ks * 16 + 8 + 2 * t);
            qa[ks][3] = *(const uint32_t*)(qb + 8 * DMODEL + ks * 16 + 8 + 2 * t);
        }
    }

    float o[8][4];
#pragma unroll
    for (int j = 0; j < 8; j++)
#pragma unroll
        for (int k = 0; k < 4; k++) o[j][k] = 0.0f;
    float l_lo = 0.0f, l_hi = 0.0f;

    const unsigned int* mbL = maskbits + growL * (SEQ / 32);
    const unsigned int* mbH = mbL + 8 * (SEQ / 32);

    auto issue = [&](int stg, int kt) {
        const size_t rowbase = (size_t)b * SEQ + kt * 64;
#pragma unroll
        for (int i = 0; i < 4; i++) {
            int f = tid + i * 128;
            int row = f >> 3, ch = f & 7;
            size_t src = (rowbase + row) * DMODEL + h * HDIM + ch * 8;
            cp_async16(ksB + (stg * TSTAGE + row * TPITCH) * 2 + ch * 16, &Km[src]);
            cp_async16(vsB + (stg * TSTAGE + row * TPITCH) * 2 + ch * 16, &Vm[src]);
        }
    };

    issue(0, 0);
    asm volatile("cp.async.commit_group;");

    const int NKT = SEQ / 64;
    for (int kt = 0; kt < NKT; kt++) {
        if (kt + 1 < NKT) issue((kt + 1) & 1, kt + 1);
        asm volatile("cp.async.commit_group;");
        asm volatile("cp.async.wait_group 1;");
        __syncthreads();

        const uint32_t kBase = ksB + (kt & 1) * TSTAGE * 2;
        const uint32_t vBase = vsB + (kt & 1) * TSTAGE * 2;

        // S = Q K^T, f16 accumulators
        uint32_t S16[8][2];
#pragma unroll
        for (int j = 0; j < 8; j++) { S16[j][0] = 0; S16[j][1] = 0; }
#pragma unroll
        for (int ks = 0; ks < 4; ks++) {
            uint32_t bK[8][2];
#pragma unroll
            for (int p = 0; p < 4; p++) {
                int key = p * 16 + ((tsel & 2) ? 8 : 0) + r;
                int d = ks * 16 + ((tsel & 1) ? 8 : 0);
                uint32_t rr[4];
                ldm_x4(rr, kBase + key * (TPITCH * 2) + d * 2);
                bK[2 * p][0] = rr[0]; bK[2 * p][1] = rr[1];
                bK[2 * p + 1][0] = rr[2]; bK[2 * p + 1][1] = rr[3];
            }
#pragma unroll
            for (int j = 0; j < 8; j++)
                mma_f16c16(S16[j], qa[ks], bK[j]);
        }

        // Fused SMAX + mask subtract, ex2 -> P (A-frag layout)
        {
            unsigned w0L = mbL[kt * 2], w1L = mbL[kt * 2 + 1];
            unsigned w0H = mbH[kt * 2], w1H = mbH[kt * 2 + 1];
            const int sh = 2 * t;
            auto squash = [&](unsigned w) {
                unsigned x = (w >> sh) & 0x03030303u;
                x |= x >> 4;
                x &= 0x00330033u;
                x |= x >> 8;
                return x & 0xFFFFu;
            };
            unsigned mfL = squash(w0L) | (squash(w1L) << 16);
            unsigned mfH = squash(w0H) | (squash(w1H) << 16);
            uint32_t suml = 0, sumh = 0;
#pragma unroll
            for (int j = 0; j < 8; j++) {
                unsigned fL = mfL >> (4 * j), fH = mfH >> (4 * j);
                uint32_t mw0 = ((fL & 1u) ? 0x7BFFu : 0x4400u)
                             | ((fL & 2u) ? 0x7BFF0000u : 0x44000000u);
                uint32_t mw1 = ((fH & 1u) ? 0x7BFFu : 0x4400u)
                             | ((fH & 2u) ? 0x7BFF0000u : 0x44000000u);
                asm("sub.f16x2 %0, %0, %1;" : "+r"(S16[j][0]) : "r"(mw0));
                asm("sub.f16x2 %0, %0, %1;" : "+r"(S16[j][1]) : "r"(mw1));
                asm("ex2.approx.f16x2 %0, %0;" : "+r"(S16[j][0]));
                asm("ex2.approx.f16x2 %0, %0;" : "+r"(S16[j][1]));
                asm("add.f16x2 %0, %0, %1;" : "+r"(suml) : "r"(S16[j][0]));
                asm("add.f16x2 %0, %0, %1;" : "+r"(sumh) : "r"(S16[j][1]));
            }
            __half2 hl = *reinterpret_cast<__half2*>(&suml);
            __half2 hh = *reinterpret_cast<__half2*>(&sumh);
            l_lo += __low2float(hl) + __high2float(hl);
            l_hi += __low2float(hh) + __high2float(hh);
        }

        // O += P V  (f32 accumulators)
#pragma unroll
        for (int ks = 0; ks < 4; ks++) {
            uint32_t pa[4] = {S16[2*ks][0], S16[2*ks][1],
                              S16[2*ks+1][0], S16[2*ks+1][1]};
            uint32_t bV[8][2];
#pragma unroll
            for (int p = 0; p < 4; p++) {
                int key = ks * 16 + ((tsel & 1) ? 8 : 0) + r;
                int d = p * 16 + ((tsel & 2) ? 8 : 0);
                uint32_t rr[4];
                ldm_x4_t(rr, vBase + key * (TPITCH * 2) + d * 2);
                bV[2 * p][0] = rr[0]; bV[2 * p][1] = rr[1];
                bV[2 * p + 1][0] = rr[2]; bV[2 * p + 1][1] = rr[3];
            }
#pragma unroll
            for (int j = 0; j < 8; j++)
                mma_f16(o[j], pa, bV[j], o[j]);
        }
        __syncthreads();
    }

    // Final cross-lane l reduction
    l_lo += __shfl_xor_sync(0xffffffffu, l_lo, 1, 4);
    l_lo += __shfl_xor_sync(0xffffffffu, l_lo, 2, 4);
    l_hi += __shfl_xor_sync(0xffffffffu, l_hi, 1, 4);
    l_hi += __shfl_xor_sync(0xffffffffu, l_hi, 2, 4);

    const float inv_lo = 1.0f / l_lo;
    const float inv_hi = 1.0f / l_hi;
    float* obase = out + growL * DMODEL + h * HDIM;
#pragma unroll
    for (int j = 0; j < 8; j++) {
        int col = j * 8 + 2 * t;
        *(float2*)(obase + col) =
            make_float2(o[j][0] * inv_lo, o[j][1] * inv_lo);
        *(float2*)(obase + 8 * DMODEL + col) =
            make_float2(o[j][2] * inv_hi, o[j][3] * inv_hi);
    }
}

// ---------------------------------------------------------------------------
// Residual + LayerNorm; DUAL also writes fp16 copy
// ---------------------------------------------------------------------------
template<bool DUAL>
__global__ __launch_bounds__(128)
void ln_kernel(const float* __restrict__ a, const float* __restrict__ bb,
               const float* __restrict__ gamma, const float* __restrict__ beta,
               float* __restrict__ out, uint16_t* __restrict__ out_b) {
    __shared__ float red[4];
    const int row = blockIdx.x;
    const int tid = threadIdx.x;
    const size_t base = (size_t)row * DMODEL + tid * 4;

    float4 av = *(const float4*)(a + base);
    float4 bv = *(const float4*)(bb + base);
    float x0 = av.x + bv.x, x1 = av.y + bv.y;
    float x2 = av.z + bv.z, x3 = av.w + bv.w;

    float sum = x0 + x1 + x2 + x3;
#pragma unroll
    for (int o = 16; o; o >>= 1) sum += __shfl_xor_sync(0xffffffffu, sum, o);
    if ((tid & 31) == 0) red[tid >> 5] = sum;
    __syncthreads();
    float mean = (red[0] + red[1] + red[2] + red[3]) * (1.0f / DMODEL);
    __syncthreads();

    float d0 = x0 - mean, d1 = x1 - mean, d2 = x2 - mean, d3 = x3 - mean;
    float sq = d0 * d0 + d1 * d1 + d2 * d2 + d3 * d3;
#pragma unroll
    for (int o = 16; o; o >>= 1) sq += __shfl_xor_sync(0xffffffffu, sq, o);
    if ((tid & 31) == 0) red[tid >> 5] = sq;
    __syncthreads();
    float var = (red[0] + red[1] + red[2] + red[3]) * (1.0f / DMODEL);
    float rs = rsqrtf(var + 1e-5f);

    float4 gv = *(const float4*)(gamma + tid * 4);
    float4 be = *(const float4*)(beta + tid * 4);
    float y0 = d0 * rs * gv.x + be.x;
    float y1 = d1 * rs * gv.y + be.y;
    float y2 = d2 * rs * gv.z + be.z;
    float y3 = d3 * rs * gv.w + be.w;
    *(float4*)(out + base) = make_float4(y0, y1, y2, y3);
    if (DUAL) {
        ((uint2*)out_b)[base / 4] =
            make_uint2(packf16(y0, y1), packf16(y2, y3));
    }
}

// ---------------------------------------------------------------------------
// Launch: fork mask + w1/w2 conversion onto a side stream, join before use.
// ---------------------------------------------------------------------------
extern "C" void kernel_launch(void* const* d_in, const int* in_sizes, int n_in,
                              void* d_out, int out_size) {
    const float* edge_x    = (const float*)d_in[0];
    const void*  edge_mask =               d_in[1];
    const float* Wqkv      = (const float*)d_in[2];
    const float* bqkv      = (const float*)d_in[3];
    const float* W1        = (const float*)d_in[4];
    const float* b1        = (const float*)d_in[5];
    const float* W2        = (const float*)d_in[6];
    const float* b2        = (const float*)d_in[7];
    const float* gamma1    = (const float*)d_in[8];
    const float* beta1     = (const float*)d_in[9];
    const float* gamma2    = (const float*)d_in[10];
    const float* beta2     = (const float*)d_in[11];
    float* out = (float*)d_out;

    float *attnout, *x1, *ff2;
    uint16_t *qb, *kb, *vb, *xb, *wqkvb, *w1b, *w2b, *x1b, *ffb;
    unsigned int* maskbits;
    cudaGetSymbolAddress((void**)&qb,       g_q);
    cudaGetSymbolAddress((void**)&kb,       g_k);
    cudaGetSymbolAddress((void**)&vb,       g_v);
    cudaGetSymbolAddress((void**)&xb,       g_xb);
    cudaGetSymbolAddress((void**)&wqkvb,    g_wqkvb);
    cudaGetSymbolAddress((void**)&w1b,      g_w1b);
    cudaGetSymbolAddress((void**)&w2b,      g_w2b);
    cudaGetSymbolAddress((void**)&attnout,  g_attnout);
    cudaGetSymbolAddress((void**)&x1,       g_x1);
    cudaGetSymbolAddress((void**)&x1b,      g_x1b);
    cudaGetSymbolAddress((void**)&ffb,      g_ffb);
    cudaGetSymbolAddress((void**)&ff2,      g_ff2);
    cudaGetSymbolAddress((void**)&maskbits, g_maskbits);

    cudaFuncSetAttribute(gemm_qkv_f16,
                         cudaFuncAttributeMaxDynamicSharedMemorySize, GEMM_SMEM);
    cudaFuncSetAttribute(gemm_f16<true, true>,
                         cudaFuncAttributeMaxDynamicSharedMemorySize, GEMM_SMEM);
    cudaFuncSetAttribute(gemm_f16<false, false>,
                         cudaFuncAttributeMaxDynamicSharedMemorySize, GEMM_SMEM);
    cudaFuncSetAttribute(attn_kernel,
                         cudaFuncAttributeMaxDynamicSharedMemorySize, ATTN_SMEM);

    static cudaStream_t s_side = nullptr;
    static cudaEvent_t  e_fork = nullptr, e_mask = nullptr, e_w12 = nullptr;
    if (s_side == nullptr) {
        cudaStreamCreateWithFlags(&s_side, cudaStreamNonBlocking);
        cudaEventCreateWithFlags(&e_fork, cudaEventDisableTiming);
        cudaEventCreateWithFlags(&e_mask, cudaEventDisableTiming);
        cudaEventCreateWithFlags(&e_w12,  cudaEventDisableTiming);
    }

    // Fork: side stream runs mask + w1/w2 conversion
    cudaEventRecord(e_fork, 0);
    cudaStreamWaitEvent(s_side, e_fork, 0);
    mask_kernel<<<2048, 256, 0, s_side>>>(edge_mask, maskbits, BSZ * SEQ * SEQ);
    cudaEventRecord(e_mask, s_side);
    convert_w12_kernel<<<512, 256, 0, s_side>>>(W1, W2, w1b, w2b);
    cudaEventRecord(e_w12, s_side);

    // Main stream: x/wqkv conversion -> QKV GEMM
    convert_main_kernel<<<2432, 256>>>(edge_x, Wqkv, xb, wqkvb);
    gemm_qkv_f16<<<dim3(QKVD / 128, NROWS / 128), 256, GEMM_SMEM>>>(
        xb, wqkvb, bqkv, qb, kb, vb);

    // Join mask before attention
    cudaStreamWaitEvent(0, e_mask, 0);
    attn_kernel<<<dim3(SEQ / 64, BSZ * NHEAD), 128, ATTN_SMEM>>>(
        qb, kb, vb, maskbits, attnout);

    ln_kernel<true><<<NROWS, 128>>>(edge_x, attnout, gamma1, beta1, x1, x1b);

    // Join w1/w2 conversion before the FFN GEMMs
    cudaStreamWaitEvent(0, e_w12, 0);
    gemm_f16<true, true><<<dim3(DMODEL / 128, NROWS / 128), 256, GEMM_SMEM>>>(
        x1b, w1b, b1, nullptr, ffb, NROWS, DMODEL, DMODEL);

    gemm_f16<false, false><<<dim3(DMODEL / 128, NROWS / 128), 256, GEMM_SMEM>>>(
        ffb, w2b, b2, ff2, nullptr, NROWS, DMODEL, DMODEL);

    ln_kernel<false><<<NROWS, 128>>>(x1, ff2, gamma2, beta2, out, nullptr);
}

// round 17
// speedup vs baseline: 1.0267x; 1.0002x over previous
#include <cuda_runtime.h>
#include <cuda_fp16.h>
#include <cstdint>

#define BSZ    8
#define SEQ    1024
#define DMODEL 512
#define NHEAD  8
#define HDIM   64
#define NROWS  (BSZ*SEQ)
#define QKVD   (3*DMODEL)

// Q pre-scale: hd^-0.5 * log2(e)  (scores in log2 domain)
#define QSCALE 0.1803368801111204f

// ---------------------------------------------------------------------------
// Scratch
// ---------------------------------------------------------------------------
__device__ uint16_t g_q      [NROWS * DMODEL];
__device__ uint16_t g_k      [NROWS * DMODEL];
__device__ uint16_t g_v      [NROWS * DMODEL];
__device__ uint16_t g_xb     [NROWS * DMODEL];
__device__ uint16_t g_wqkvb  [DMODEL * QKVD];
__device__ uint16_t g_w1b    [DMODEL * DMODEL];
__device__ uint16_t g_w2b    [DMODEL * DMODEL];
__device__ float    g_attnout[NROWS * DMODEL];
__device__ float    g_x1     [NROWS * DMODEL];
__device__ uint16_t g_x1b    [NROWS * DMODEL];
__device__ uint16_t g_ffb    [NROWS * DMODEL];
__device__ float    g_ff2    [NROWS * DMODEL];
__device__ unsigned g_maskbits[NROWS * (SEQ/32)];

// ---------------------------------------------------------------------------
// helpers
// ---------------------------------------------------------------------------
__device__ __forceinline__ uint32_t packf16(float lo, float hi) {
    uint32_t r;
    asm("cvt.rn.f16x2.f32 %0, %1, %2;" : "=r"(r) : "f"(hi), "f"(lo));
    return r;
}
__device__ __forceinline__ void mma_f16(float d[4], const uint32_t a[4],
                                        const uint32_t b[2], const float c[4]) {
    asm volatile(
        "mma.sync.aligned.m16n8k16.row.col.f32.f16.f16.f32 "
        "{%0,%1,%2,%3}, {%4,%5,%6,%7}, {%8,%9}, {%10,%11,%12,%13};"
        : "=f"(d[0]), "=f"(d[1]), "=f"(d[2]), "=f"(d[3])
        : "r"(a[0]), "r"(a[1]), "r"(a[2]), "r"(a[3]), "r"(b[0]), "r"(b[1]),
          "f"(c[0]), "f"(c[1]), "f"(c[2]), "f"(c[3]));
}
// f16-accumulator variant (2x tensor rate; C/D are 2 packed f16x2 regs)
__device__ __forceinline__ void mma_f16c16(uint32_t d[2], const uint32_t a[4],
                                           const uint32_t b[2]) {
    asm volatile(
        "mma.sync.aligned.m16n8k16.row.col.f16.f16.f16.f16 "
        "{%0,%1}, {%2,%3,%4,%5}, {%6,%7}, {%0,%1};"
        : "+r"(d[0]), "+r"(d[1])
        : "r"(a[0]), "r"(a[1]), "r"(a[2]), "r"(a[3]), "r"(b[0]), "r"(b[1]));
}
__device__ __forceinline__ void cp_async16(uint32_t dst, const void* src) {
    asm volatile("cp.async.cg.shared.global [%0], [%1], 16;"
                 :: "r"(dst), "l"(src));
}
__device__ __forceinline__ void ldm_x4(uint32_t r[4], uint32_t addr) {
    asm volatile("ldmatrix.sync.aligned.m8n8.x4.shared.b16 {%0,%1,%2,%3}, [%4];"
                 : "=r"(r[0]), "=r"(r[1]), "=r"(r[2]), "=r"(r[3]) : "r"(addr));
}
__device__ __forceinline__ void ldm_x4_t(uint32_t r[4], uint32_t addr) {
    asm volatile("ldmatrix.sync.aligned.m8n8.x4.trans.shared.b16 {%0,%1,%2,%3}, [%4];"
                 : "=r"(r[0]), "=r"(r[1]), "=r"(r[2]), "=r"(r[3]) : "r"(addr));
}

// ---------------------------------------------------------------------------
// Mask: per-block dtype detection + vectorized bit expansion
// ---------------------------------------------------------------------------
__global__ __launch_bounds__(256)
void mask_kernel(const void* __restrict__ m, unsigned* __restrict__ out, int n) {
    __shared__ int s3f, soff;
    if (threadIdx.x == 0) { s3f = 0; soff = 0; }
    __syncthreads();
    {
        uint4 v = ((const uint4*)m)[threadIdx.x];
        unsigned w[4] = {v.x, v.y, v.z, v.w};
        int l3f = 0, loff = 0;
#pragma unroll
        for (int j = 0; j < 4; j++) {
            unsigned x = w[j];
            if (((x & 0xFF) == 0x3F) || (((x >> 8) & 0xFF) == 0x3F) ||
                (((x >> 16) & 0xFF) == 0x3F) || (((x >> 24) & 0xFF) == 0x3F))
                l3f++;
            if (x & 0xFFFFFF00u) loff++;
        }
        if (l3f) atomicAdd(&s3f, 1);
        if (loff) atomicAdd(&soff, 1);
    }
    __syncthreads();
    const int kind = (s3f > 0) ? 2 : ((soff > 0) ? 0 : 1);

    const int nthreads = gridDim.x * blockDim.x;
    const int nchunk = n / 16;
    for (int idx = blockIdx.x * blockDim.x + threadIdx.x; idx < nchunk;
         idx += nthreads) {
        unsigned bits = 0;
        if (kind == 0) {
            uint4 v = ((const uint4*)m)[idx];
            unsigned w[4] = {v.x, v.y, v.z, v.w};
#pragma unroll
            for (int j = 0; j < 4; j++)
#pragma unroll
                for (int bpos = 0; bpos < 4; bpos++)
                    if ((w[j] >> (8 * bpos)) & 0xFFu)
                        bits |= 1u << (j * 4 + bpos);
        } else {
            const uint4* p = (const uint4*)m + idx * 4;
#pragma unroll
            for (int j = 0; j < 4; j++) {
                uint4 v = p[j];
                if (v.x) bits |= 1u << (j * 4 + 0);
                if (v.y) bits |= 1u << (j * 4 + 1);
                if (v.z) bits |= 1u << (j * 4 + 2);
                if (v.w) bits |= 1u << (j * 4 + 3);
            }
        }
        unsigned other = __shfl_xor_sync(0xffffffffu, bits, 1);
        if ((threadIdx.x & 1) == 0)
            out[idx >> 1] = bits | (other << 16);
    }
}

// ---------------------------------------------------------------------------
// Conversions -> fp16
// ---------------------------------------------------------------------------
#define NX4 (NROWS*DMODEL/4)
#define NW4 (DMODEL*QKVD/4)
#define NF4 (DMODEL*DMODEL/4)

__global__ __launch_bounds__(256)
void convert_main_kernel(const float* __restrict__ x,
                         const float* __restrict__ wqkv,
                         uint16_t* __restrict__ xb,
                         uint16_t* __restrict__ wqkvb) {
    const int total = NX4 + NW4;
    const int stride = gridDim.x * blockDim.x;
    for (int i = blockIdx.x * blockDim.x + threadIdx.x; i < total; i += stride) {
        const float4* src;
        uint2* dst;
        int j;
        if (i < NX4) { j = i;       src = (const float4*)x    + j; dst = (uint2*)xb    + j; }
        else         { j = i - NX4; src = (const float4*)wqkv + j; dst = (uint2*)wqkvb + j; }
        float4 v = *src;
        *dst = make_uint2(packf16(v.x, v.y), packf16(v.z, v.w));
    }
}

__global__ __launch_bounds__(256)
void convert_w12_kernel(const float* __restrict__ w1, const float* __restrict__ w2,
                        uint16_t* __restrict__ w1b, uint16_t* __restrict__ w2b) {
    const int total = 2 * NF4;
    const int stride = gridDim.x * blockDim.x;
    for (int i = blockIdx.x * blockDim.x + threadIdx.x; i < total; i += stride) {
        const float4* src;
        uint2* dst;
        int j;
        if (i < NF4) { j = i;       src = (const float4*)w1 + j; dst = (uint2*)w1b + j; }
        else         { j = i - NF4; src = (const float4*)w2 + j; dst = (uint2*)w2b + j; }
        float4 v = *src;
        *dst = make_uint2(packf16(v.x, v.y), packf16(v.z, v.w));
    }
}

// ---------------------------------------------------------------------------
// GEMM tiles: 128x128, BK=64, 2-stage cp.async (dynamic smem), ldmatrix.
// A [row][k] pitch 72 u16; B [k][n] pitch 136 u16.
// ---------------------------------------------------------------------------
#define GA_PITCH 72
#define GB_PITCH 136
#define GA_STAGE (128*GA_PITCH)   // u16
#define GB_STAGE (64*GB_PITCH)    // u16
#define GEMM_SMEM (2*(GA_STAGE+GB_STAGE)*2)   // 71680 B

// QKV GEMM: f16 accumulators (2x rate), writes Q (scaled) / K / V fp16.
__global__ __launch_bounds__(256)
void gemm_qkv_f16(const uint16_t* __restrict__ A, const uint16_t* __restrict__ B,
                  const float* __restrict__ bias,
                  uint16_t* __restrict__ Qo, uint16_t* __restrict__ Ko,
                  uint16_t* __restrict__ Vo) {
    extern __shared__ uint16_t dynsmem[];
    uint16_t* As = dynsmem;
    uint16_t* Bs = dynsmem + 2 * GA_STAGE;
    const int K = DMODEL, N = QKVD;
    const int bm = blockIdx.y * 128, bn = blockIdx.x * 128;
    const int tid = threadIdx.x;
    const int wid = tid >> 5, lane = tid & 31;
    const int g = lane >> 2, t = lane & 3;
    const int wm = (wid >> 1) * 32, wn = (wid & 1) * 64;
    const int tsel = lane >> 3, r = lane & 7;

    const uint32_t asB = (uint32_t)__cvta_generic_to_shared(As);
    const uint32_t bsB = (uint32_t)__cvta_generic_to_shared(Bs);

    uint32_t acc16[2][8][2];
#pragma unroll
    for (int i = 0; i < 2; i++)
#pragma unroll
        for (int j = 0; j < 8; j++) { acc16[i][j][0] = 0; acc16[i][j][1] = 0; }

    auto issue = [&](int stg, int k0) {
        // A: 128 rows x 64 k = 1024 chunks of 8 u16
#pragma unroll
        for (int i = 0; i < 4; i++) {
            int f = tid + i * 256;
            int row = f >> 3, ch = f & 7;
            cp_async16(asB + (stg * GA_STAGE + row * GA_PITCH) * 2 + ch * 16,
                       &A[(size_t)(bm + row) * K + k0 + ch * 8]);
        }
        // B: 64 rows x 128 n = 1024 chunks
#pragma unroll
        for (int i = 0; i < 4; i++) {
            int f = tid + i * 256;
            int row = f >> 4, ch = f & 15;
            cp_async16(bsB + (stg * GB_STAGE + row * GB_PITCH) * 2 + ch * 16,
                       &B[(size_t)(k0 + row) * N + bn + ch * 8]);
        }
    };

    const int NIT = K / 64;   // 8
    issue(0, 0);
    asm volatile("cp.async.commit_group;");

    for (int it = 0; it < NIT; ++it) {
        int cur = it & 1;
        if (it + 1 < NIT) issue((it + 1) & 1, (it + 1) * 64);
        asm volatile("cp.async.commit_group;");
        asm volatile("cp.async.wait_group 1;");
        __syncthreads();

        uint32_t aBase = asB + cur * GA_STAGE * 2;
        uint32_t bBase = bsB + cur * GB_STAGE * 2;
#pragma unroll
        for (int ks = 0; ks < 64; ks += 16) {
            uint32_t aF[2][4];
#pragma unroll
            for (int mt = 0; mt < 2; mt++) {
                int row = wm + mt * 16 + ((tsel & 1) ? 8 : 0) + r;
                int col = ks + ((tsel & 2) ? 8 : 0);
                ldm_x4(aF[mt], aBase + row * (GA_PITCH * 2) + col * 2);
            }
            uint32_t bF[8][2];
#pragma unroll
            for (int p = 0; p < 4; p++) {
                int krow = ks + ((tsel & 1) ? 8 : 0) + r;
                int ncol = wn + p * 16 + ((tsel & 2) ? 8 : 0);
                uint32_t rr[4];
                ldm_x4_t(rr, bBase + krow * (GB_PITCH * 2) + ncol * 2);
                bF[2 * p][0] = rr[0]; bF[2 * p][1] = rr[1];
                bF[2 * p + 1][0] = rr[2]; bF[2 * p + 1][1] = rr[3];
            }
#pragma unroll
            for (int mt = 0; mt < 2; mt++)
#pragma unroll
                for (int nt = 0; nt < 8; nt++)
                    mma_f16c16(acc16[mt][nt], aF[mt], bF[nt]);
        }
        __syncthreads();
    }

#pragma unroll
    for (int mt = 0; mt < 2; mt++) {
        int row = bm + wm + mt * 16 + g;
#pragma unroll
        for (int nt = 0; nt < 8; nt++) {
            int col = bn + wn + nt * 8 + 2 * t;
            float b0 = bias[col], b1 = bias[col + 1];
            __half2 lo2 = *reinterpret_cast<__half2*>(&acc16[mt][nt][0]);
            __half2 hi2 = *reinterpret_cast<__half2*>(&acc16[mt][nt][1]);
            float c0 = __low2float(lo2) + b0;
            float c1 = __high2float(lo2) + b1;
            float c2 = __low2float(hi2) + b0;
            float c3 = __high2float(hi2) + b1;
            if (col < DMODEL) {
                *(uint32_t*)&Qo[(size_t)row * DMODEL + col] =
                    packf16(c0 * QSCALE, c1 * QSCALE);
                *(uint32_t*)&Qo[(size_t)(row + 8) * DMODEL + col] =
                    packf16(c2 * QSCALE, c3 * QSCALE);
            } else if (col < 2 * DMODEL) {
                int ck = col - DMODEL;
                *(uint32_t*)&Ko[(size_t)row * DMODEL + ck] = packf16(c0, c1);
                *(uint32_t*)&Ko[(size_t)(row + 8) * DMODEL + ck] = packf16(c2, c3);
            } else {
                int cv = col - 2 * DMODEL;
                *(uint32_t*)&Vo[(size_t)row * DMODEL + cv] = packf16(c0, c1);
                *(uint32_t*)&Vo[(size_t)(row + 8) * DMODEL + cv] = packf16(c2, c3);
            }
        }
    }
}

// FFN GEMM: f32 accumulators (precision-critical path), BK=64, 2-stage.
template<bool RELU, bool OUTHF>
__global__ __launch_bounds__(256)
void gemm_f16(const uint16_t* __restrict__ A, const uint16_t* __restrict__ B,
              const float* __restrict__ bias, float* __restrict__ Cf,
              uint16_t* __restrict__ Cb, int M, int N, int K) {
    extern __shared__ uint16_t dynsmem[];
    uint16_t* As = dynsmem;
    uint16_t* Bs = dynsmem + 2 * GA_STAGE;
    const int bm = blockIdx.y * 128, bn = blockIdx.x * 128;
    const int tid = threadIdx.x;
    const int wid = tid >> 5, lane = tid & 31;
    const int g = lane >> 2, t = lane & 3;
    const int wm = (wid >> 1) * 32, wn = (wid & 1) * 64;
    const int tsel = lane >> 3, r = lane & 7;

    const uint32_t asB = (uint32_t)__cvta_generic_to_shared(As);
    const uint32_t bsB = (uint32_t)__cvta_generic_to_shared(Bs);

    float acc[2][8][4];
#pragma unroll
    for (int i = 0; i < 2; i++)
#pragma unroll
        for (int j = 0; j < 8; j++)
#pragma unroll
            for (int k = 0; k < 4; k++) acc[i][j][k] = 0.0f;

    auto issue = [&](int stg, int k0) {
#pragma unroll
        for (int i = 0; i < 4; i++) {
            int f = tid + i * 256;
            int row = f >> 3, ch = f & 7;
            cp_async16(asB + (stg * GA_STAGE + row * GA_PITCH) * 2 + ch * 16,
                       &A[(size_t)(bm + row) * K + k0 + ch * 8]);
        }
#pragma unroll
        for (int i = 0; i < 4; i++) {
            int f = tid + i * 256;
            int row = f >> 4, ch = f & 15;
            cp_async16(bsB + (stg * GB_STAGE + row * GB_PITCH) * 2 + ch * 16,
                       &B[(size_t)(k0 + row) * N + bn + ch * 8]);
        }
    };

    const int NIT = K / 64;
    issue(0, 0);
    asm volatile("cp.async.commit_group;");

    for (int it = 0; it < NIT; ++it) {
        int cur = it & 1;
        if (it + 1 < NIT) issue((it + 1) & 1, (it + 1) * 64);
        asm volatile("cp.async.commit_group;");
        asm volatile("cp.async.wait_group 1;");
        __syncthreads();

        uint32_t aBase = asB + cur * GA_STAGE * 2;
        uint32_t bBase = bsB + cur * GB_STAGE * 2;
#pragma unroll
        for (int ks = 0; ks < 64; ks += 16) {
            uint32_t aF[2][4];
#pragma unroll
            for (int mt = 0; mt < 2; mt++) {
                int row = wm + mt * 16 + ((tsel & 1) ? 8 : 0) + r;
                int col = ks + ((tsel & 2) ? 8 : 0);
                ldm_x4(aF[mt], aBase + row * (GA_PITCH * 2) + col * 2);
            }
            uint32_t bF[8][2];
#pragma unroll
            for (int p = 0; p < 4; p++) {
                int krow = ks + ((tsel & 1) ? 8 : 0) + r;
                int ncol = wn + p * 16 + ((tsel & 2) ? 8 : 0);
                uint32_t rr[4];
                ldm_x4_t(rr, bBase + krow * (GB_PITCH * 2) + ncol * 2);
                bF[2 * p][0] = rr[0]; bF[2 * p][1] = rr[1];
                bF[2 * p + 1][0] = rr[2]; bF[2 * p + 1][1] = rr[3];
            }
#pragma unroll
            for (int mt = 0; mt < 2; mt++)
#pragma unroll
                for (int nt = 0; nt < 8; nt++)
                    mma_f16(acc[mt][nt], aF[mt], bF[nt], acc[mt][nt]);
        }
        __syncthreads();
    }

#pragma unroll
    for (int mt = 0; mt < 2; mt++) {
        int row = bm + wm + mt * 16 + g;
#pragma unroll
        for (int nt = 0; nt < 8; nt++) {
            int col = bn + wn + nt * 8 + 2 * t;
            float b0 = bias[col], b1 = bias[col + 1];
            float c0 = acc[mt][nt][0] + b0;
            float c1 = acc[mt][nt][1] + b1;
            float c2 = acc[mt][nt][2] + b0;
            float c3 = acc[mt][nt][3] + b1;
            if (RELU) {
                c0 = fmaxf(c0, 0.0f); c1 = fmaxf(c1, 0.0f);
                c2 = fmaxf(c2, 0.0f); c3 = fmaxf(c3, 0.0f);
            }
            if (OUTHF) {
                *(uint32_t*)&Cb[(size_t)row * N + col] = packf16(c0, c1);
                *(uint32_t*)&Cb[(size_t)(row + 8) * N + col] = packf16(c2, c3);
            } else {
                *(float2*)&Cf[(size_t)row * N + col] = make_float2(c0, c1);
                *(float2*)&Cf[(size_t)(row + 8) * N + col] = make_float2(c2, c3);
            }
        }
    }
}

// ---------------------------------------------------------------------------
// FlashAttention (R10 core, best measured): 64 q-rows/block, fp16 QK^T with
// f16 acc, fused SMAX+mask, ex2.f16x2, f32 PV acc, 2-stage cp.async K/V.
// ---------------------------------------------------------------------------
#define TPITCH 72
#define TSTAGE (64*TPITCH)
#define ATTN_SMEM (2*TSTAGE*2*2)   // 36864 B

__global__ __launch_bounds__(128)
void attn_kernel(const uint16_t* __restrict__ Qm, const uint16_t* __restrict__ Km,
                 const uint16_t* __restrict__ Vm,
                 const unsigned int* __restrict__ maskbits,
                 float* __restrict__ out) {
    extern __shared__ uint16_t dynsmem[];
    uint16_t* Ks = dynsmem;
    uint16_t* Vs = dynsmem + 2 * TSTAGE;

    const int qt = blockIdx.x;
    const int bh = blockIdx.y;
    const int b = bh >> 3, h = bh & 7;
    const int tid = threadIdx.x;
    const int wid = tid >> 5, lane = tid & 31;
    const int g = lane >> 2, t = lane & 3;
    const int tsel = lane >> 3, r = lane & 7;
    const int r0 = wid * 16;

    const int qrow_lo = qt * 64 + r0 + g;
    const size_t growL = (size_t)b * SEQ + qrow_lo;

    const uint32_t ksB = (uint32_t)__cvta_generic_to_shared(Ks);
    const uint32_t vsB = (uint32_t)__cvta_generic_to_shared(Vs);

    uint32_t qa[4][4];
    {
        const uint16_t* qb = Qm + growL * DMODEL + h * HDIM;
#pragma unroll
        for (int ks = 0; ks < 4; ks++) {
            qa[ks][0] = *(const uint32_t*)(qb + ks * 16 + 2 * t);
            qa[ks][1] = *(const uint32_t*)(qb + 8 * DMODEL + ks * 16 + 2 * t);
            qa[ks][2] = *(const uint32_t*)(qb + ks * 16 + 8 + 2 * t);
            qa[ks][3] = *(const uint32_t*)(qb + 8 * DMODEL + ks * 16 + 8 + 2 * t);
        }
    }

    float o[8][4];
#pragma unroll
    for (int j = 0; j < 8; j++)
#pragma unroll
        for (int k = 0; k < 4; k++) o[j][k] = 0.0f;
    float l_lo = 0.0f, l_hi = 0.0f;

    const unsigned int* mbL = maskbits + growL * (SEQ / 32);
    const unsigned int* mbH = mbL + 8 * (SEQ / 32);

    auto issue = [&](int stg, int kt) {
        const size_t rowbase = (size_t)b * SEQ + kt * 64;
#pragma unroll
        for (int i = 0; i < 4; i++) {
            int f = tid + i * 128;
            int row = f >> 3, ch = f & 7;
            size_t src = (rowbase + row) * DMODEL + h * HDIM + ch * 8;
            cp_async16(ksB + (stg * TSTAGE + row * TPITCH) * 2 + ch * 16, &Km[src]);
            cp_async16(vsB + (stg * TSTAGE + row * TPITCH) * 2 + ch * 16, &Vm[src]);
        }
    };

    issue(0, 0);
    asm volatile("cp.async.commit_group;");

    const int NKT = SEQ / 64;
    for (int kt = 0; kt < NKT; kt++) {
        if (kt + 1 < NKT) issue((kt + 1) & 1, kt + 1);
        asm volatile("cp.async.commit_group;");
        asm volatile("cp.async.wait_group 1;");
        __syncthreads();

        const uint32_t kBase = ksB + (kt & 1) * TSTAGE * 2;
        const uint32_t vBase = vsB + (kt & 1) * TSTAGE * 2;

        // S = Q K^T, f16 accumulators
        uint32_t S16[8][2];
#pragma unroll
        for (int j = 0; j < 8; j++) { S16[j][0] = 0; S16[j][1] = 0; }
#pragma unroll
        for (int ks = 0; ks < 4; ks++) {
            uint32_t bK[8][2];
#pragma unroll
            for (int p = 0; p < 4; p++) {
                int key = p * 16 + ((tsel & 2) ? 8 : 0) + r;
                int d = ks * 16 + ((tsel & 1) ? 8 : 0);
                uint32_t rr[4];
                ldm_x4(rr, kBase + key * (TPITCH * 2) + d * 2);
                bK[2 * p][0] = rr[0]; bK[2 * p][1] = rr[1];
                bK[2 * p + 1][0] = rr[2]; bK[2 * p + 1][1] = rr[3];
            }
#pragma unroll
            for (int j = 0; j < 8; j++)
                mma_f16c16(S16[j], qa[ks], bK[j]);
        }

        // Fused SMAX + mask subtract, ex2 -> P (A-frag layout)
        {
            unsigned w0L = mbL[kt * 2], w1L = mbL[kt * 2 + 1];
            unsigned w0H = mbH[kt * 2], w1H = mbH[kt * 2 + 1];
            const int sh = 2 * t;
            auto squash = [&](unsigned w) {
                unsigned x = (w >> sh) & 0x03030303u;
                x |= x >> 4;
                x &= 0x00330033u;
                x |= x >> 8;
                return x & 0xFFFFu;
            };
            unsigned mfL = squash(w0L) | (squash(w1L) << 16);
            unsigned mfH = squash(w0H) | (squash(w1H) << 16);
            uint32_t suml = 0, sumh = 0;
#pragma unroll
            for (int j = 0; j < 8; j++) {
                unsigned fL = mfL >> (4 * j), fH = mfH >> (4 * j);
                uint32_t mw0 = ((fL & 1u) ? 0x7BFFu : 0x4400u)
                             | ((fL & 2u) ? 0x7BFF0000u : 0x44000000u);
                uint32_t mw1 = ((fH & 1u) ? 0x7BFFu : 0x4400u)
                             | ((fH & 2u) ? 0x7BFF0000u : 0x44000000u);
                asm("sub.f16x2 %0, %0, %1;" : "+r"(S16[j][0]) : "r"(mw0));
                asm("sub.f16x2 %0, %0, %1;" : "+r"(S16[j][1]) : "r"(mw1));
                asm("ex2.approx.f16x2 %0, %0;" : "+r"(S16[j][0]));
                asm("ex2.approx.f16x2 %0, %0;" : "+r"(S16[j][1]));
                asm("add.f16x2 %0, %0, %1;" : "+r"(suml) : "r"(S16[j][0]));
                asm("add.f16x2 %0, %0, %1;" : "+r"(sumh) : "r"(S16[j][1]));
            }
            __half2 hl = *reinterpret_cast<__half2*>(&suml);
            __half2 hh = *reinterpret_cast<__half2*>(&sumh);
            l_lo += __low2float(hl) + __high2float(hl);
            l_hi += __low2float(hh) + __high2float(hh);
        }

        // O += P V  (f32 accumulators)
#pragma unroll
        for (int ks = 0; ks < 4; ks++) {
            uint32_t pa[4] = {S16[2*ks][0], S16[2*ks][1],
                              S16[2*ks+1][0], S16[2*ks+1][1]};
            uint32_t bV[8][2];
#pragma unroll
            for (int p = 0; p < 4; p++) {
                int key = ks * 16 + ((tsel & 1) ? 8 : 0) + r;
                int d = p * 16 + ((tsel & 2) ? 8 : 0);
                uint32_t rr[4];
                ldm_x4_t(rr, vBase + key * (TPITCH * 2) + d * 2);
                bV[2 * p][0] = rr[0]; bV[2 * p][1] = rr[1];
                bV[2 * p + 1][0] = rr[2]; bV[2 * p + 1][1] = rr[3];
            }
#pragma unroll
            for (int j = 0; j < 8; j++)
                mma_f16(o[j], pa, bV[j], o[j]);
        }
        __syncthreads();
    }

    // Final cross-lane l reduction
    l_lo += __shfl_xor_sync(0xffffffffu, l_lo, 1, 4);
    l_lo += __shfl_xor_sync(0xffffffffu, l_lo, 2, 4);
    l_hi += __shfl_xor_sync(0xffffffffu, l_hi, 1, 4);
    l_hi += __shfl_xor_sync(0xffffffffu, l_hi, 2, 4);

    const float inv_lo = 1.0f / l_lo;
    const float inv_hi = 1.0f / l_hi;
    float* obase = out + growL * DMODEL + h * HDIM;
#pragma unroll
    for (int j = 0; j < 8; j++) {
        int col = j * 8 + 2 * t;
        *(float2*)(obase + col) =
            make_float2(o[j][0] * inv_lo, o[j][1] * inv_lo);
        *(float2*)(obase + 8 * DMODEL + col) =
            make_float2(o[j][2] * inv_hi, o[j][3] * inv_hi);
    }
}

// ---------------------------------------------------------------------------
// Residual + LayerNorm; DUAL also writes fp16 copy
// ---------------------------------------------------------------------------
template<bool DUAL>
__global__ __launch_bounds__(128)
void ln_kernel(const float* __restrict__ a, const float* __restrict__ bb,
               const float* __restrict__ gamma, const float* __restrict__ beta,
               float* __restrict__ out, uint16_t* __restrict__ out_b) {
    __shared__ float red[4];
    const int row = blockIdx.x;
    const int tid = threadIdx.x;
    const size_t base = (size_t)row * DMODEL + tid * 4;

    float4 av = *(const float4*)(a + base);
    float4 bv = *(const float4*)(bb + base);
    float x0 = av.x + bv.x, x1 = av.y + bv.y;
    float x2 = av.z + bv.z, x3 = av.w + bv.w;

    float sum = x0 + x1 + x2 + x3;
#pragma unroll
    for (int o = 16; o; o >>= 1) sum += __shfl_xor_sync(0xffffffffu, sum, o);
    if ((tid & 31) == 0) red[tid >> 5] = sum;
    __syncthreads();
    float mean = (red[0] + red[1] + red[2] + red[3]) * (1.0f / DMODEL);
    __syncthreads();

    float d0 = x0 - mean, d1 = x1 - mean, d2 = x2 - mean, d3 = x3 - mean;
    float sq = d0 * d0 + d1 * d1 + d2 * d2 + d3 * d3;
#pragma unroll
    for (int o = 16; o; o >>= 1) sq += __shfl_xor_sync(0xffffffffu, sq, o);
    if ((tid & 31) == 0) red[tid >> 5] = sq;
    __syncthreads();
    float var = (red[0] + red[1] + red[2] + red[3]) * (1.0f / DMODEL);
    float rs = rsqrtf(var + 1e-5f);

    float4 gv = *(const float4*)(gamma + tid * 4);
    float4 be = *(const float4*)(beta + tid * 4);
    float y0 = d0 * rs * gv.x + be.x;
    float y1 = d1 * rs * gv.y + be.y;
    float y2 = d2 * rs * gv.z + be.z;
    float y3 = d3 * rs * gv.w + be.w;
    *(float4*)(out + base) = make_float4(y0, y1, y2, y3);
    if (DUAL) {
        ((uint2*)out_b)[base / 4] =
            make_uint2(packf16(y0, y1), packf16(y2, y3));
    }
}

// ---------------------------------------------------------------------------
// Launch: fork mask + w1/w2 conversion onto a side stream, join before use.
// ---------------------------------------------------------------------------
extern "C" void kernel_launch(void* const* d_in, const int* in_sizes, int n_in,
                              void* d_out, int out_size) {
    const float* edge_x    = (const float*)d_in[0];
    const void*  edge_mask =               d_in[1];
    const float* Wqkv      = (const float*)d_in[2];
    const float* bqkv      = (const float*)d_in[3];
    const float* W1        = (const float*)d_in[4];
    const float* b1        = (const float*)d_in[5];
    const float* W2        = (const float*)d_in[6];
    const float* b2        = (const float*)d_in[7];
    const float* gamma1    = (const float*)d_in[8];
    const float* beta1     = (const float*)d_in[9];
    const float* gamma2    = (const float*)d_in[10];
    const float* beta2     = (const float*)d_in[11];
    float* out = (float*)d_out;

    float *attnout, *x1, *ff2;
    uint16_t *qb, *kb, *vb, *xb, *wqkvb, *w1b, *w2b, *x1b, *ffb;
    unsigned int* maskbits;
    cudaGetSymbolAddress((void**)&qb,       g_q);
    cudaGetSymbolAddress((void**)&kb,       g_k);
    cudaGetSymbolAddress((void**)&vb,       g_v);
    cudaGetSymbolAddress((void**)&xb,       g_xb);
    cudaGetSymbolAddress((void**)&wqkvb,    g_wqkvb);
    cudaGetSymbolAddress((void**)&w1b,      g_w1b);
    cudaGetSymbolAddress((void**)&w2b,      g_w2b);
    cudaGetSymbolAddress((void**)&attnout,  g_attnout);
    cudaGetSymbolAddress((void**)&x1,       g_x1);
    cudaGetSymbolAddress((void**)&x1b,      g_x1b);
    cudaGetSymbolAddress((void**)&ffb,      g_ffb);
    cudaGetSymbolAddress((void**)&ff2,      g_ff2);
    cudaGetSymbolAddress((void**)&maskbits, g_maskbits);

    cudaFuncSetAttribute(gemm_qkv_f16,
                         cudaFuncAttributeMaxDynamicSharedMemorySize, GEMM_SMEM);
    cudaFuncSetAttribute(gemm_f16<true, true>,
                         cudaFuncAttributeMaxDynamicSharedMemorySize, GEMM_SMEM);
    cudaFuncSetAttribute(gemm_f16<false, false>,
                         cudaFuncAttributeMaxDynamicSharedMemorySize, GEMM_SMEM);
    cudaFuncSetAttribute(attn_kernel,
                         cudaFuncAttributeMaxDynamicSharedMemorySize, ATTN_SMEM);

    static cudaStream_t s_side = nullptr;
    static cudaEvent_t  e_fork = nullptr, e_mask = nullptr, e_w12 = nullptr;
    if (s_side == nullptr) {
        cudaStreamCreateWithFlags(&s_side, cudaStreamNonBlocking);
        cudaEventCreateWithFlags(&e_fork, cudaEventDisableTiming);
        cudaEventCreateWithFlags(&e_mask, cudaEventDisableTiming);
        cudaEventCreateWithFlags(&e_w12,  cudaEventDisableTiming);
    }

    // Fork: side stream runs mask + w1/w2 conversion
    cudaEventRecord(e_fork, 0);
    cudaStreamWaitEvent(s_side, e_fork, 0);
    mask_kernel<<<2048, 256, 0, s_side>>>(edge_mask, maskbits, BSZ * SEQ * SEQ);
    cudaEventRecord(e_mask, s_side);
    convert_w12_kernel<<<512, 256, 0, s_side>>>(W1, W2, w1b, w2b);
    cudaEventRecord(e_w12, s_side);

    // Main stream: x/wqkv conversion -> QKV GEMM
    convert_main_kernel<<<2432, 256>>>(edge_x, Wqkv, xb, wqkvb);
    gemm_qkv_f16<<<dim3(QKVD / 128, NROWS / 128), 256, GEMM_SMEM>>>(
        xb, wqkvb, bqkv, qb, kb, vb);

    // Join mask before attention
    cudaStreamWaitEvent(0, e_mask, 0);
    attn_kernel<<<dim3(SEQ / 64, BSZ * NHEAD), 128, ATTN_SMEM>>>(
        qb, kb, vb, maskbits, attnout);

    ln_kernel<true><<<NROWS, 128>>>(edge_x, attnout, gamma1, beta1, x1, x1b);

    // Join w1/w2 conversion before the FFN GEMMs
    cudaStreamWaitEvent(0, e_w12, 0);
    gemm_f16<true, true><<<dim3(DMODEL / 128, NROWS / 128), 256, GEMM_SMEM>>>(
        x1b, w1b, b1, nullptr, ffb, NROWS, DMODEL, DMODEL);

    gemm_f16<false, false><<<dim3(DMODEL / 128, NROWS / 128), 256, GEMM_SMEM>>>(
        ffb, w2b, b2, ff2, nullptr, NROWS, DMODEL, DMODEL);

    ln_kernel<false><<<NROWS, 128>>>(x1, ff2, gamma2, beta2, out, nullptr);
}